// round 3
// baseline (speedup 1.0000x reference)
#include <cuda_runtime.h>
#include <cuda_bf16.h>
#include <cstdint>

// Problem constants
// B=16, H=W=64, HW=4096, DIM=256, NH=8, CPH=8, CR=64, 3*CR=192, KA=3
#define Bn   16
#define HW   4096
#define IMG  64
#define DIMC 256
#define NHn  8
#define CPHn 8
#define QKVC 192
#define CRn  64
#define SCALE 0.17677669529663687f   // 32^-0.5

// Scratch (device globals: allowed; no runtime allocation)
__device__ float g_qkv[(size_t)Bn * QKVC * HW];    // [b][192][4096]  ~50 MB
__device__ float g_o64[(size_t)Bn * CRn * HW];     // [b][64][4096]   ~17 MB

// ---------------------------------------------------------------------------
// Kernel 1: QKV GEMM.  Y[b][m][hw] = sum_k W[m][k] * X[b][k][hw] + bias[m]
// M=192 (2 tiles of 96), N=65536 (tiles of 128), K=256 (chunks of 32)
// ---------------------------------------------------------------------------
__global__ __launch_bounds__(256) void qkv_gemm_kernel(
    const float* __restrict__ X, const float* __restrict__ W,
    const float* __restrict__ bias)
{
    __shared__ float xs[32][128];
    __shared__ float ws[96][33];

    const int col0 = blockIdx.x * 128;          // global column (b,hw)
    const int b    = col0 >> 12;
    const int hw0  = col0 & 4095;
    const int m0   = blockIdx.y * 96;
    const int tid  = threadIdx.x;
    const int rg   = tid >> 4;                  // 0..15 (6 rows each)
    const int cg   = tid & 15;                  // 0..15 (8 cols each)

    const float* Xb = X + (size_t)b * (DIMC * HW) + hw0;

    float acc[6][8];
#pragma unroll
    for (int r = 0; r < 6; r++)
#pragma unroll
        for (int c = 0; c < 8; c++) acc[r][c] = 0.f;

    for (int k0 = 0; k0 < DIMC; k0 += 32) {
        // load X tile: 32x128
#pragma unroll
        for (int i = 0; i < 16; i++) {
            int idx = tid + i * 256;
            int kk = idx >> 7, cc = idx & 127;
            xs[kk][cc] = Xb[(size_t)(k0 + kk) * HW + cc];
        }
        // load W tile: 96x32
#pragma unroll
        for (int i = 0; i < 12; i++) {
            int idx = tid + i * 256;
            int m = idx >> 5, kk = idx & 31;
            ws[m][kk] = W[(m0 + m) * DIMC + k0 + kk];
        }
        __syncthreads();

#pragma unroll
        for (int kk = 0; kk < 32; kk++) {
            float a[6];
#pragma unroll
            for (int r = 0; r < 6; r++) a[r] = ws[rg * 6 + r][kk];
            float4 b0 = *(const float4*)&xs[kk][cg * 8];
            float4 b1 = *(const float4*)&xs[kk][cg * 8 + 4];
            float bb[8] = {b0.x, b0.y, b0.z, b0.w, b1.x, b1.y, b1.z, b1.w};
#pragma unroll
            for (int r = 0; r < 6; r++)
#pragma unroll
                for (int c = 0; c < 8; c++)
                    acc[r][c] = fmaf(a[r], bb[c], acc[r][c]);
        }
        __syncthreads();
    }

    // epilogue
#pragma unroll
    for (int r = 0; r < 6; r++) {
        int row = m0 + rg * 6 + r;
        float bv = bias[row];
        float* Yp = g_qkv + (size_t)b * (QKVC * HW) + (size_t)row * HW + hw0 + cg * 8;
        float4 s0 = make_float4(acc[r][0] + bv, acc[r][1] + bv, acc[r][2] + bv, acc[r][3] + bv);
        float4 s1 = make_float4(acc[r][4] + bv, acc[r][5] + bv, acc[r][6] + bv, acc[r][7] + bv);
        *(float4*)(Yp)     = s0;
        *(float4*)(Yp + 4) = s1;
    }
}

// ---------------------------------------------------------------------------
// Kernel 2: fused unfold-conv + slide attention.
// grid: (16 spatial tiles, NH, B), block 256 = 16x16 pixels.
// ---------------------------------------------------------------------------
__global__ __launch_bounds__(256) void attn_kernel(
    const float* __restrict__ w1g,     // dep_conv1_w  [72][9]
    const float* __restrict__ b0g,     // dep_conv_b   [72]
    const float* __restrict__ b1g,     // dep_conv1_b  [72]
    const float* __restrict__ rpbg)    // rpb_table    [8][9]
{
    __shared__ float kk_s[CPHn][18][18];
    __shared__ float vv_s[CPHn][18][18];
    __shared__ float w1[648];
    __shared__ float bs[72];
    __shared__ float rpb[9];

    const int tile = blockIdx.x;
    const int n    = blockIdx.y;
    const int b    = blockIdx.z;
    const int ty0  = (tile >> 2) << 4;
    const int tx0  = (tile & 3) << 4;
    const int tid  = threadIdx.x;

    for (int i = tid; i < 648; i += 256) w1[i] = w1g[i];
    if (tid < 72) bs[tid] = b0g[tid] + b1g[tid];
    if (tid < 9)  rpb[tid] = rpbg[n * 9 + tid];

    const float* base_k = g_qkv + (size_t)b * (QKVC * HW) + (size_t)(n * 24 + 8)  * HW;
    const float* base_v = g_qkv + (size_t)b * (QKVC * HW) + (size_t)(n * 24 + 16) * HW;

    // load 18x18 halos for 8 channels of kk and vv (zero padding at borders)
    for (int i = tid; i < CPHn * 324; i += 256) {
        int g  = i / 324;
        int r  = i - g * 324;
        int hy = r / 18, hx = r - hy * 18;
        int gy = ty0 - 1 + hy, gx = tx0 - 1 + hx;
        bool ok = (unsigned)gy < 64u && (unsigned)gx < 64u;
        int off = g * HW + gy * IMG + gx;
        ((float*)kk_s)[i] = ok ? base_k[off] : 0.f;
        ((float*)vv_s)[i] = ok ? base_v[off] : 0.f;
    }
    __syncthreads();

    const int ly = tid >> 4, lx = tid & 15;
    const int hw = (ty0 + ly) * IMG + (tx0 + lx);

    const float* base_q = g_qkv + (size_t)b * (QKVC * HW) + (size_t)(n * 24) * HW + hw;
    float q[CPHn], qsum = 0.f;
#pragma unroll
    for (int g = 0; g < CPHn; g++) {
        q[g] = base_q[(size_t)g * HW] * SCALE;
        qsum += q[g];
    }

    float lg[9];
#pragma unroll
    for (int j = 0; j < 9; j++) lg[j] = rpb[j] * qsum;

    // logits: sum_g q_g * k_{g,j}
#pragma unroll
    for (int g = 0; g < CPHn; g++) {
        float r[9];
#pragma unroll
        for (int th = 0; th < 3; th++)
#pragma unroll
            for (int tw = 0; tw < 3; tw++)
                r[th * 3 + tw] = kk_s[g][ly + th][lx + tw];
#pragma unroll
        for (int j = 0; j < 9; j++) {
            const float* wj = &w1[(g * 9 + j) * 9];
            float kj = r[j] + bs[g * 9 + j];
#pragma unroll
            for (int t = 0; t < 9; t++) kj = fmaf(wj[t], r[t], kj);
            lg[j] = fmaf(q[g], kj, lg[j]);
        }
    }

    // softmax over 9
    float mx = lg[0];
#pragma unroll
    for (int j = 1; j < 9; j++) mx = fmaxf(mx, lg[j]);
    float s = 0.f;
#pragma unroll
    for (int j = 0; j < 9; j++) { lg[j] = __expf(lg[j] - mx); s += lg[j]; }
    float inv = 1.f / s;
#pragma unroll
    for (int j = 0; j < 9; j++) lg[j] *= inv;

    // out_g = sum_j attn_j * v_{g,j}
    float* ob = g_o64 + (size_t)b * (CRn * HW) + (size_t)(n * CPHn) * HW + hw;
#pragma unroll
    for (int g = 0; g < CPHn; g++) {
        float r[9];
#pragma unroll
        for (int th = 0; th < 3; th++)
#pragma unroll
            for (int tw = 0; tw < 3; tw++)
                r[th * 3 + tw] = vv_s[g][ly + th][lx + tw];
        float og = 0.f;
#pragma unroll
        for (int j = 0; j < 9; j++) {
            const float* wj = &w1[(g * 9 + j) * 9];
            float vj = r[j] + bs[g * 9 + j];
#pragma unroll
            for (int t = 0; t < 9; t++) vj = fmaf(wj[t], r[t], vj);
            og = fmaf(lg[j], vj, og);
        }
        ob[(size_t)g * HW] = og;
    }
}

// ---------------------------------------------------------------------------
// Kernel 3: projection GEMM. OUT[b][m][hw] = sum_k Wp[m][k]*O64[b][k][hw] + pb[m]
// M=256 (2 tiles of 128), N=65536 (tiles of 128), K=64 (chunks of 32)
// ---------------------------------------------------------------------------
__global__ __launch_bounds__(256) void proj_gemm_kernel(
    const float* __restrict__ W, const float* __restrict__ bias,
    float* __restrict__ OUT)
{
    __shared__ float xs[32][128];
    __shared__ float ws[128][33];

    const int col0 = blockIdx.x * 128;
    const int b    = col0 >> 12;
    const int hw0  = col0 & 4095;
    const int m0   = blockIdx.y * 128;
    const int tid  = threadIdx.x;
    const int rg   = tid >> 4;     // 16 rowgroups of 8
    const int cg   = tid & 15;     // 16 colgroups of 8

    const float* Xb = g_o64 + (size_t)b * (CRn * HW) + hw0;

    float acc[8][8];
#pragma unroll
    for (int r = 0; r < 8; r++)
#pragma unroll
        for (int c = 0; c < 8; c++) acc[r][c] = 0.f;

    for (int k0 = 0; k0 < CRn; k0 += 32) {
#pragma unroll
        for (int i = 0; i < 16; i++) {
            int idx = tid + i * 256;
            int kk = idx >> 7, cc = idx & 127;
            xs[kk][cc] = Xb[(size_t)(k0 + kk) * HW + cc];
        }
#pragma unroll
        for (int i = 0; i < 16; i++) {
            int idx = tid + i * 256;
            int m = idx >> 5, kk = idx & 31;
            ws[m][kk] = W[(m0 + m) * CRn + k0 + kk];
        }
        __syncthreads();

#pragma unroll
        for (int kk = 0; kk < 32; kk++) {
            float a[8];
#pragma unroll
            for (int r = 0; r < 8; r++) a[r] = ws[rg * 8 + r][kk];
            float4 b0 = *(const float4*)&xs[kk][cg * 8];
            float4 b1 = *(const float4*)&xs[kk][cg * 8 + 4];
            float bb[8] = {b0.x, b0.y, b0.z, b0.w, b1.x, b1.y, b1.z, b1.w};
#pragma unroll
            for (int r = 0; r < 8; r++)
#pragma unroll
                for (int c = 0; c < 8; c++)
                    acc[r][c] = fmaf(a[r], bb[c], acc[r][c]);
        }
        __syncthreads();
    }

#pragma unroll
    for (int r = 0; r < 8; r++) {
        int row = m0 + rg * 8 + r;
        float bv = bias[row];
        float* Yp = OUT + (size_t)b * (DIMC * HW) + (size_t)row * HW + hw0 + cg * 8;
        float4 s0 = make_float4(acc[r][0] + bv, acc[r][1] + bv, acc[r][2] + bv, acc[r][3] + bv);
        float4 s1 = make_float4(acc[r][4] + bv, acc[r][5] + bv, acc[r][6] + bv, acc[r][7] + bv);
        *(float4*)(Yp)     = s0;
        *(float4*)(Yp + 4) = s1;
    }
}

// ---------------------------------------------------------------------------
// Launch. Inputs (metadata order — 13 inputs!):
// 0:x 1:H22 2:W22 3:relative_pos_index 4:relative_coords_table
// 5:qkv_w 6:qkv_b 7:dep_conv_b 8:dep_conv1_w 9:dep_conv1_b
// 10:rpb_table 11:proj_w 12:proj_b
// ---------------------------------------------------------------------------
extern "C" void kernel_launch(void* const* d_in, const int* in_sizes, int n_in,
                              void* d_out, int out_size)
{
    const float* x      = (const float*)d_in[0];
    const float* qkv_w  = (const float*)d_in[5];
    const float* qkv_b  = (const float*)d_in[6];
    const float* dcb    = (const float*)d_in[7];
    const float* dc1w   = (const float*)d_in[8];
    const float* dc1b   = (const float*)d_in[9];
    const float* rpb    = (const float*)d_in[10];
    const float* proj_w = (const float*)d_in[11];
    const float* proj_b = (const float*)d_in[12];
    float* out = (float*)d_out;

    qkv_gemm_kernel<<<dim3(512, 2), 256>>>(x, qkv_w, qkv_b);
    attn_kernel<<<dim3(16, NHn, Bn), 256>>>(dc1w, dcb, dc1b, rpb);
    proj_gemm_kernel<<<dim3(512, 2), 256>>>(proj_w, proj_b, out);
}

// round 4
// speedup vs baseline: 1.3735x; 1.3735x over previous
#include <cuda_runtime.h>
#include <cuda_bf16.h>
#include <cstdint>

// Problem constants
// B=16, H=W=64, HW=4096, DIM=256, NH=8, CPH=8, CR=64, 3*CR=192, KA=3
#define Bn   16
#define HW   4096
#define IMG  64
#define DIMC 256
#define NHn  8
#define CPHn 8
#define QKVC 192
#define CRn  64
#define SCALE 0.17677669529663687f   // 32^-0.5

// Scratch (device globals: allowed; no runtime allocation)
__device__ float g_qkv[(size_t)Bn * QKVC * HW];    // [b][192][4096]  ~50 MB
__device__ float g_o64[(size_t)Bn * CRn * HW];     // [b][64][4096]   ~17 MB

// ---------------------------------------------------------------------------
// Kernel 1: QKV GEMM.  Y[b][m][hw] = sum_k W[m][k] * X[b][k][hw] + bias[m]
// (unchanged from passing R3 kernel)
// ---------------------------------------------------------------------------
__global__ __launch_bounds__(256) void qkv_gemm_kernel(
    const float* __restrict__ X, const float* __restrict__ W,
    const float* __restrict__ bias)
{
    __shared__ float xs[32][128];
    __shared__ float ws[96][33];

    const int col0 = blockIdx.x * 128;
    const int b    = col0 >> 12;
    const int hw0  = col0 & 4095;
    const int m0   = blockIdx.y * 96;
    const int tid  = threadIdx.x;
    const int rg   = tid >> 4;
    const int cg   = tid & 15;

    const float* Xb = X + (size_t)b * (DIMC * HW) + hw0;

    float acc[6][8];
#pragma unroll
    for (int r = 0; r < 6; r++)
#pragma unroll
        for (int c = 0; c < 8; c++) acc[r][c] = 0.f;

    for (int k0 = 0; k0 < DIMC; k0 += 32) {
#pragma unroll
        for (int i = 0; i < 16; i++) {
            int idx = tid + i * 256;
            int kk = idx >> 7, cc = idx & 127;
            xs[kk][cc] = Xb[(size_t)(k0 + kk) * HW + cc];
        }
#pragma unroll
        for (int i = 0; i < 12; i++) {
            int idx = tid + i * 256;
            int m = idx >> 5, kk = idx & 31;
            ws[m][kk] = W[(m0 + m) * DIMC + k0 + kk];
        }
        __syncthreads();

#pragma unroll
        for (int kk = 0; kk < 32; kk++) {
            float a[6];
#pragma unroll
            for (int r = 0; r < 6; r++) a[r] = ws[rg * 6 + r][kk];
            float4 b0 = *(const float4*)&xs[kk][cg * 8];
            float4 b1 = *(const float4*)&xs[kk][cg * 8 + 4];
            float bb[8] = {b0.x, b0.y, b0.z, b0.w, b1.x, b1.y, b1.z, b1.w};
#pragma unroll
            for (int r = 0; r < 6; r++)
#pragma unroll
                for (int c = 0; c < 8; c++)
                    acc[r][c] = fmaf(a[r], bb[c], acc[r][c]);
        }
        __syncthreads();
    }

#pragma unroll
    for (int r = 0; r < 6; r++) {
        int row = m0 + rg * 6 + r;
        float bv = bias[row];
        float* Yp = g_qkv + (size_t)b * (QKVC * HW) + (size_t)row * HW + hw0 + cg * 8;
        float4 s0 = make_float4(acc[r][0] + bv, acc[r][1] + bv, acc[r][2] + bv, acc[r][3] + bv);
        float4 s1 = make_float4(acc[r][4] + bv, acc[r][5] + bv, acc[r][6] + bv, acc[r][7] + bv);
        *(float4*)(Yp)     = s0;
        *(float4*)(Yp + 4) = s1;
    }
}

// ---------------------------------------------------------------------------
// Kernel 2 (REWRITTEN): fused unfold-conv + slide attention.
// Tile 32x16 pixels per block; 256 threads; each thread = 2 vertical pixels.
// Conv taps cached in registers r[4][3], shared across the 2 pixels; weight
// broadcasts amortized over 2 pixels and 20 FMAs.
// grid: (8 spatial tiles, NH, B)
// ---------------------------------------------------------------------------
#define TSX 32
#define TSY 16

__global__ __launch_bounds__(256) void attn_kernel(
    const float* __restrict__ w1g,     // dep_conv1_w  [72][9]
    const float* __restrict__ b0g,     // dep_conv_b   [72]
    const float* __restrict__ b1g,     // dep_conv1_b  [72]
    const float* __restrict__ rpbg)    // rpb_table    [8][9]
{
    __shared__ float kk_s[CPHn][TSY + 2][TSX + 2];   // 8*18*34
    __shared__ float vv_s[CPHn][TSY + 2][TSX + 2];
    __shared__ float w1[648];
    __shared__ float bs[72];
    __shared__ float rpb[9];

    const int tile = blockIdx.x;          // 0..7 : 2 x-tiles * 4 y-tiles
    const int n    = blockIdx.y;
    const int b    = blockIdx.z;
    const int ty0  = (tile >> 1) * TSY;
    const int tx0  = (tile & 1) * TSX;
    const int tid  = threadIdx.x;
    const int tx   = tid & 31;            // column within tile
    const int tyg  = tid >> 5;            // 0..7 -> rows tyg*2, tyg*2+1

    for (int i = tid; i < 648; i += 256) w1[i] = w1g[i];
    if (tid < 72) bs[tid] = b0g[tid] + b1g[tid];
    if (tid < 9)  rpb[tid] = rpbg[n * 9 + tid];

    const float* base_k = g_qkv + (size_t)b * (QKVC * HW) + (size_t)(n * 24 + 8)  * HW;
    const float* base_v = g_qkv + (size_t)b * (QKVC * HW) + (size_t)(n * 24 + 16) * HW;

    // halo load: 8 channels x 18 x 34, zero-padded at image borders
    const int HALO = (TSY + 2) * (TSX + 2);   // 612
    for (int i = tid; i < CPHn * HALO; i += 256) {
        int g   = i / HALO;
        int rem = i - g * HALO;
        int hy  = rem / (TSX + 2);
        int hx  = rem - hy * (TSX + 2);
        int gy  = ty0 - 1 + hy, gx = tx0 - 1 + hx;
        bool ok = (unsigned)gy < 64u && (unsigned)gx < 64u;
        int off = g * HW + gy * IMG + gx;
        ((float*)kk_s)[i] = ok ? base_k[off] : 0.f;
        ((float*)vv_s)[i] = ok ? base_v[off] : 0.f;
    }
    __syncthreads();

    // per-thread pixels: (ty0 + tyg*2 + p, tx0 + tx), p = 0,1
    const int hw0 = (ty0 + tyg * 2) * IMG + (tx0 + tx);
    const float* base_q = g_qkv + (size_t)b * (QKVC * HW) + (size_t)(n * 24) * HW + hw0;

    float qv[CPHn][2];
    float qsum0 = 0.f, qsum1 = 0.f;
#pragma unroll
    for (int g = 0; g < CPHn; g++) {
        qv[g][0] = base_q[(size_t)g * HW]       * SCALE;
        qv[g][1] = base_q[(size_t)g * HW + IMG] * SCALE;
        qsum0 += qv[g][0];
        qsum1 += qv[g][1];
    }

    float lg[2][9];
#pragma unroll
    for (int j = 0; j < 9; j++) {
        lg[0][j] = rpb[j] * qsum0;
        lg[1][j] = rpb[j] * qsum1;
    }

    // ---- K phase: logits ----
#pragma unroll
    for (int g = 0; g < CPHn; g++) {
        float r[4][3];
#pragma unroll
        for (int rr = 0; rr < 4; rr++)
#pragma unroll
            for (int cc = 0; cc < 3; cc++)
                r[rr][cc] = kk_s[g][tyg * 2 + rr][tx + cc];
#pragma unroll
        for (int j = 0; j < 9; j++) {
            const int jh = j / 3, jw = j % 3;
            const float* wj = &w1[(g * 9 + j) * 9];
            float w[9];
#pragma unroll
            for (int t = 0; t < 9; t++) w[t] = wj[t];
            const float bj = bs[g * 9 + j];
#pragma unroll
            for (int p = 0; p < 2; p++) {
                float kj = r[p + jh][jw] + bj;
#pragma unroll
                for (int t = 0; t < 9; t++)
                    kj = fmaf(w[t], r[p + t / 3][t % 3], kj);
                lg[p][j] = fmaf(qv[g][p], kj, lg[p][j]);
            }
        }
    }

    // ---- softmax over 9 (per pixel) ----
#pragma unroll
    for (int p = 0; p < 2; p++) {
        float mx = lg[p][0];
#pragma unroll
        for (int j = 1; j < 9; j++) mx = fmaxf(mx, lg[p][j]);
        float s = 0.f;
#pragma unroll
        for (int j = 0; j < 9; j++) { lg[p][j] = __expf(lg[p][j] - mx); s += lg[p][j]; }
        float inv = 1.f / s;
#pragma unroll
        for (int j = 0; j < 9; j++) lg[p][j] *= inv;
    }

    // ---- V phase: weighted sum ----
    float* ob = g_o64 + (size_t)b * (CRn * HW) + (size_t)(n * CPHn) * HW + hw0;
#pragma unroll
    for (int g = 0; g < CPHn; g++) {
        float s[4][3];
#pragma unroll
        for (int rr = 0; rr < 4; rr++)
#pragma unroll
            for (int cc = 0; cc < 3; cc++)
                s[rr][cc] = vv_s[g][tyg * 2 + rr][tx + cc];
        float og0 = 0.f, og1 = 0.f;
#pragma unroll
        for (int j = 0; j < 9; j++) {
            const int jh = j / 3, jw = j % 3;
            const float* wj = &w1[(g * 9 + j) * 9];
            float w[9];
#pragma unroll
            for (int t = 0; t < 9; t++) w[t] = wj[t];
            const float bj = bs[g * 9 + j];

            float v0 = s[0 + jh][jw] + bj;
            float v1 = s[1 + jh][jw] + bj;
#pragma unroll
            for (int t = 0; t < 9; t++) {
                v0 = fmaf(w[t], s[0 + t / 3][t % 3], v0);
                v1 = fmaf(w[t], s[1 + t / 3][t % 3], v1);
            }
            og0 = fmaf(lg[0][j], v0, og0);
            og1 = fmaf(lg[1][j], v1, og1);
        }
        ob[(size_t)g * HW]       = og0;
        ob[(size_t)g * HW + IMG] = og1;
    }
}

// ---------------------------------------------------------------------------
// Kernel 3: projection GEMM (unchanged from passing R3 kernel)
// ---------------------------------------------------------------------------
__global__ __launch_bounds__(256) void proj_gemm_kernel(
    const float* __restrict__ W, const float* __restrict__ bias,
    float* __restrict__ OUT)
{
    __shared__ float xs[32][128];
    __shared__ float ws[128][33];

    const int col0 = blockIdx.x * 128;
    const int b    = col0 >> 12;
    const int hw0  = col0 & 4095;
    const int m0   = blockIdx.y * 128;
    const int tid  = threadIdx.x;
    const int rg   = tid >> 4;
    const int cg   = tid & 15;

    const float* Xb = g_o64 + (size_t)b * (CRn * HW) + hw0;

    float acc[8][8];
#pragma unroll
    for (int r = 0; r < 8; r++)
#pragma unroll
        for (int c = 0; c < 8; c++) acc[r][c] = 0.f;

    for (int k0 = 0; k0 < CRn; k0 += 32) {
#pragma unroll
        for (int i = 0; i < 16; i++) {
            int idx = tid + i * 256;
            int kk = idx >> 7, cc = idx & 127;
            xs[kk][cc] = Xb[(size_t)(k0 + kk) * HW + cc];
        }
#pragma unroll
        for (int i = 0; i < 16; i++) {
            int idx = tid + i * 256;
            int m = idx >> 5, kk = idx & 31;
            ws[m][kk] = W[(m0 + m) * CRn + k0 + kk];
        }
        __syncthreads();

#pragma unroll
        for (int kk = 0; kk < 32; kk++) {
            float a[8];
#pragma unroll
            for (int r = 0; r < 8; r++) a[r] = ws[rg * 8 + r][kk];
            float4 b0 = *(const float4*)&xs[kk][cg * 8];
            float4 b1 = *(const float4*)&xs[kk][cg * 8 + 4];
            float bb[8] = {b0.x, b0.y, b0.z, b0.w, b1.x, b1.y, b1.z, b1.w};
#pragma unroll
            for (int r = 0; r < 8; r++)
#pragma unroll
                for (int c = 0; c < 8; c++)
                    acc[r][c] = fmaf(a[r], bb[c], acc[r][c]);
        }
        __syncthreads();
    }

#pragma unroll
    for (int r = 0; r < 8; r++) {
        int row = m0 + rg * 8 + r;
        float bv = bias[row];
        float* Yp = OUT + (size_t)b * (DIMC * HW) + (size_t)row * HW + hw0 + cg * 8;
        float4 s0 = make_float4(acc[r][0] + bv, acc[r][1] + bv, acc[r][2] + bv, acc[r][3] + bv);
        float4 s1 = make_float4(acc[r][4] + bv, acc[r][5] + bv, acc[r][6] + bv, acc[r][7] + bv);
        *(float4*)(Yp)     = s0;
        *(float4*)(Yp + 4) = s1;
    }
}

// ---------------------------------------------------------------------------
// Launch. Inputs (metadata order — 13 inputs):
// 0:x 1:H22 2:W22 3:relative_pos_index 4:relative_coords_table
// 5:qkv_w 6:qkv_b 7:dep_conv_b 8:dep_conv1_w 9:dep_conv1_b
// 10:rpb_table 11:proj_w 12:proj_b
// ---------------------------------------------------------------------------
extern "C" void kernel_launch(void* const* d_in, const int* in_sizes, int n_in,
                              void* d_out, int out_size)
{
    const float* x      = (const float*)d_in[0];
    const float* qkv_w  = (const float*)d_in[5];
    const float* qkv_b  = (const float*)d_in[6];
    const float* dcb    = (const float*)d_in[7];
    const float* dc1w   = (const float*)d_in[8];
    const float* dc1b   = (const float*)d_in[9];
    const float* rpb    = (const float*)d_in[10];
    const float* proj_w = (const float*)d_in[11];
    const float* proj_b = (const float*)d_in[12];
    float* out = (float*)d_out;

    qkv_gemm_kernel<<<dim3(512, 2), 256>>>(x, qkv_w, qkv_b);
    attn_kernel<<<dim3(8, NHn, Bn), 256>>>(dc1w, dcb, dc1b, rpb);
    proj_gemm_kernel<<<dim3(512, 2), 256>>>(proj_w, proj_b, out);
}

// round 5
// speedup vs baseline: 2.9176x; 2.1241x over previous
#include <cuda_runtime.h>
#include <cuda_bf16.h>
#include <cstdint>

// Problem constants
// B=16, H=W=64, HW=4096, DIM=256, NH=8, CPH=8, CR=64, 3*CR=192, KA=3
#define Bn   16
#define HW   4096
#define IMG  64
#define DIMC 256
#define NHn  8
#define CPHn 8
#define QKVC 192
#define CRn  64
#define SCALE 0.17677669529663687f   // 32^-0.5

// Scratch (device globals: allowed; no runtime allocation)
__device__ float g_qkv[(size_t)Bn * QKVC * HW];    // [b][192][4096]  ~50 MB
__device__ float g_o64[(size_t)Bn * CRn * HW];     // [b][64][4096]   ~17 MB

// ---------------------------------------------------------------------------
// Kernel 1: QKV GEMM (unchanged)
// ---------------------------------------------------------------------------
__global__ __launch_bounds__(256) void qkv_gemm_kernel(
    const float* __restrict__ X, const float* __restrict__ W,
    const float* __restrict__ bias)
{
    __shared__ float xs[32][128];
    __shared__ float ws[96][33];

    const int col0 = blockIdx.x * 128;
    const int b    = col0 >> 12;
    const int hw0  = col0 & 4095;
    const int m0   = blockIdx.y * 96;
    const int tid  = threadIdx.x;
    const int rg   = tid >> 4;
    const int cg   = tid & 15;

    const float* Xb = X + (size_t)b * (DIMC * HW) + hw0;

    float acc[6][8];
#pragma unroll
    for (int r = 0; r < 6; r++)
#pragma unroll
        for (int c = 0; c < 8; c++) acc[r][c] = 0.f;

    for (int k0 = 0; k0 < DIMC; k0 += 32) {
#pragma unroll
        for (int i = 0; i < 16; i++) {
            int idx = tid + i * 256;
            int kk = idx >> 7, cc = idx & 127;
            xs[kk][cc] = Xb[(size_t)(k0 + kk) * HW + cc];
        }
#pragma unroll
        for (int i = 0; i < 12; i++) {
            int idx = tid + i * 256;
            int m = idx >> 5, kk = idx & 31;
            ws[m][kk] = W[(m0 + m) * DIMC + k0 + kk];
        }
        __syncthreads();

#pragma unroll
        for (int kk = 0; kk < 32; kk++) {
            float a[6];
#pragma unroll
            for (int r = 0; r < 6; r++) a[r] = ws[rg * 6 + r][kk];
            float4 b0 = *(const float4*)&xs[kk][cg * 8];
            float4 b1 = *(const float4*)&xs[kk][cg * 8 + 4];
            float bb[8] = {b0.x, b0.y, b0.z, b0.w, b1.x, b1.y, b1.z, b1.w};
#pragma unroll
            for (int r = 0; r < 6; r++)
#pragma unroll
                for (int c = 0; c < 8; c++)
                    acc[r][c] = fmaf(a[r], bb[c], acc[r][c]);
        }
        __syncthreads();
    }

#pragma unroll
    for (int r = 0; r < 6; r++) {
        int row = m0 + rg * 6 + r;
        float bv = bias[row];
        float* Yp = g_qkv + (size_t)b * (QKVC * HW) + (size_t)row * HW + hw0 + cg * 8;
        float4 s0 = make_float4(acc[r][0] + bv, acc[r][1] + bv, acc[r][2] + bv, acc[r][3] + bv);
        float4 s1 = make_float4(acc[r][4] + bv, acc[r][5] + bv, acc[r][6] + bv, acc[r][7] + bv);
        *(float4*)(Yp)     = s0;
        *(float4*)(Yp + 4) = s1;
    }
}

// ---------------------------------------------------------------------------
// Kernel 2 (REWRITE v3): fused unfold-conv + slide attention.
// 32x32 tile, 256 threads, 4 vertical pixels/thread.
// - weights packed [72][12] in smem, bias folded at slot 9 -> 3x LDS.128/(g,j)
// - single halo buffer reused: kk for K-phase, vv for V-phase
// grid: (4 spatial tiles, NH, B)
// ---------------------------------------------------------------------------
#define TS 32
#define HAL (TS + 2)          // 34
#define HALN (HAL * HAL)      // 1156

__global__ __launch_bounds__(256) void attn_kernel(
    const float* __restrict__ w1g,     // dep_conv1_w  [72][9]
    const float* __restrict__ b0g,     // dep_conv_b   [72]
    const float* __restrict__ b1g,     // dep_conv1_b  [72]
    const float* __restrict__ rpbg)    // rpb_table    [8][9]
{
    __shared__ float hs[CPHn][HAL][HAL];   // 36.1 KB, reused kk->vv
    __shared__ float w1p[72 * 12];         // 3.4 KB, [g*9+j][0..8]=w, [9]=bias
    __shared__ float rpb[9];

    const int tile = blockIdx.x;          // 0..3 : 2x2 tiles of 32x32
    const int n    = blockIdx.y;
    const int b    = blockIdx.z;
    const int ty0  = (tile >> 1) * TS;
    const int tx0  = (tile & 1) * TS;
    const int tid  = threadIdx.x;
    const int tx   = tid & 31;            // col 0..31
    const int tr   = tid >> 5;            // 0..7 -> rows tr*4 .. tr*4+3

    // pack weights + fold bias
    for (int i = tid; i < 648; i += 256) {
        int e = i / 9, t = i - e * 9;
        w1p[e * 12 + t] = w1g[i];
    }
    if (tid < 72) w1p[tid * 12 + 9] = b0g[tid] + b1g[tid];
    if (tid < 9)  rpb[tid] = rpbg[n * 9 + tid];

    const size_t hbase = (size_t)b * (QKVC * HW) + (size_t)(n * 24) * HW;
    const float* base_q = g_qkv + hbase;
    const float* base_k = g_qkv + hbase + (size_t)8  * HW;
    const float* base_v = g_qkv + hbase + (size_t)16 * HW;

    // per-thread pixel rows: ty0 + tr*4 + p
    const int hw0 = (ty0 + tr * 4) * IMG + (tx0 + tx);

    // load q (global, independent of smem)
    float qv[CPHn][4];
    float qsum[4] = {0.f, 0.f, 0.f, 0.f};
#pragma unroll
    for (int g = 0; g < CPHn; g++) {
        const float* qp = base_q + (size_t)g * HW + hw0;
#pragma unroll
        for (int p = 0; p < 4; p++) {
            qv[g][p] = qp[p * IMG] * SCALE;
            qsum[p] += qv[g][p];
        }
    }

    // ---- load kk halo ----
#pragma unroll
    for (int g = 0; g < CPHn; g++) {
        const float* src = base_k + (size_t)g * HW;
        for (int i = tid; i < HALN; i += 256) {
            int hy = i / HAL, hx = i - hy * HAL;
            int gy = ty0 - 1 + hy, gx = tx0 - 1 + hx;
            bool ok = (unsigned)gy < 64u && (unsigned)gx < 64u;
            ((float*)hs)[g * HALN + i] = ok ? src[gy * IMG + gx] : 0.f;
        }
    }
    __syncthreads();

    float lg[4][9];
#pragma unroll
    for (int p = 0; p < 4; p++)
#pragma unroll
        for (int j = 0; j < 9; j++) lg[p][j] = rpb[j] * qsum[p];

    // ---- K phase ----
#pragma unroll
    for (int g = 0; g < CPHn; g++) {
        float t[6][3];
#pragma unroll
        for (int rr = 0; rr < 6; rr++)
#pragma unroll
            for (int cc = 0; cc < 3; cc++)
                t[rr][cc] = hs[g][tr * 4 + rr][tx + cc];
#pragma unroll
        for (int j = 0; j < 9; j++) {
            const int jh = j / 3, jw = j % 3;
            const int wb = (g * 9 + j) * 12;
            float4 wa = *(const float4*)&w1p[wb];
            float4 wc = *(const float4*)&w1p[wb + 4];
            float4 we = *(const float4*)&w1p[wb + 8];   // .x = w8, .y = bias
#pragma unroll
            for (int p = 0; p < 4; p++) {
                float kj = t[p + jh][jw] + we.y;
                kj = fmaf(wa.x, t[p][0], kj);
                kj = fmaf(wa.y, t[p][1], kj);
                kj = fmaf(wa.z, t[p][2], kj);
                kj = fmaf(wa.w, t[p + 1][0], kj);
                kj = fmaf(wc.x, t[p + 1][1], kj);
                kj = fmaf(wc.y, t[p + 1][2], kj);
                kj = fmaf(wc.z, t[p + 2][0], kj);
                kj = fmaf(wc.w, t[p + 2][1], kj);
                kj = fmaf(we.x, t[p + 2][2], kj);
                lg[p][j] = fmaf(qv[g][p], kj, lg[p][j]);
            }
        }
    }

    // ---- softmax over 9 per pixel ----
#pragma unroll
    for (int p = 0; p < 4; p++) {
        float mx = lg[p][0];
#pragma unroll
        for (int j = 1; j < 9; j++) mx = fmaxf(mx, lg[p][j]);
        float s = 0.f;
#pragma unroll
        for (int j = 0; j < 9; j++) { lg[p][j] = __expf(lg[p][j] - mx); s += lg[p][j]; }
        float inv = 1.f / s;
#pragma unroll
        for (int j = 0; j < 9; j++) lg[p][j] *= inv;
    }

    // ---- reload halo with vv ----
    __syncthreads();
#pragma unroll
    for (int g = 0; g < CPHn; g++) {
        const float* src = base_v + (size_t)g * HW;
        for (int i = tid; i < HALN; i += 256) {
            int hy = i / HAL, hx = i - hy * HAL;
            int gy = ty0 - 1 + hy, gx = tx0 - 1 + hx;
            bool ok = (unsigned)gy < 64u && (unsigned)gx < 64u;
            ((float*)hs)[g * HALN + i] = ok ? src[gy * IMG + gx] : 0.f;
        }
    }
    __syncthreads();

    // ---- V phase ----
    float* ob = g_o64 + (size_t)b * (CRn * HW) + (size_t)(n * CPHn) * HW + hw0;
#pragma unroll
    for (int g = 0; g < CPHn; g++) {
        float t[6][3];
#pragma unroll
        for (int rr = 0; rr < 6; rr++)
#pragma unroll
            for (int cc = 0; cc < 3; cc++)
                t[rr][cc] = hs[g][tr * 4 + rr][tx + cc];
        float og[4] = {0.f, 0.f, 0.f, 0.f};
#pragma unroll
        for (int j = 0; j < 9; j++) {
            const int jh = j / 3, jw = j % 3;
            const int wb = (g * 9 + j) * 12;
            float4 wa = *(const float4*)&w1p[wb];
            float4 wc = *(const float4*)&w1p[wb + 4];
            float4 we = *(const float4*)&w1p[wb + 8];
#pragma unroll
            for (int p = 0; p < 4; p++) {
                float vj = t[p + jh][jw] + we.y;
                vj = fmaf(wa.x, t[p][0], vj);
                vj = fmaf(wa.y, t[p][1], vj);
                vj = fmaf(wa.z, t[p][2], vj);
                vj = fmaf(wa.w, t[p + 1][0], vj);
                vj = fmaf(wc.x, t[p + 1][1], vj);
                vj = fmaf(wc.y, t[p + 1][2], vj);
                vj = fmaf(wc.z, t[p + 2][0], vj);
                vj = fmaf(wc.w, t[p + 2][1], vj);
                vj = fmaf(we.x, t[p + 2][2], vj);
                og[p] = fmaf(lg[p][j], vj, og[p]);
            }
        }
        float* op = ob + (size_t)g * HW;
#pragma unroll
        for (int p = 0; p < 4; p++) op[p * IMG] = og[p];
    }
}

// ---------------------------------------------------------------------------
// Kernel 3: projection GEMM (unchanged)
// ---------------------------------------------------------------------------
__global__ __launch_bounds__(256) void proj_gemm_kernel(
    const float* __restrict__ W, const float* __restrict__ bias,
    float* __restrict__ OUT)
{
    __shared__ float xs[32][128];
    __shared__ float ws[128][33];

    const int col0 = blockIdx.x * 128;
    const int b    = col0 >> 12;
    const int hw0  = col0 & 4095;
    const int m0   = blockIdx.y * 128;
    const int tid  = threadIdx.x;
    const int rg   = tid >> 4;
    const int cg   = tid & 15;

    const float* Xb = g_o64 + (size_t)b * (CRn * HW) + hw0;

    float acc[8][8];
#pragma unroll
    for (int r = 0; r < 8; r++)
#pragma unroll
        for (int c = 0; c < 8; c++) acc[r][c] = 0.f;

    for (int k0 = 0; k0 < CRn; k0 += 32) {
#pragma unroll
        for (int i = 0; i < 16; i++) {
            int idx = tid + i * 256;
            int kk = idx >> 7, cc = idx & 127;
            xs[kk][cc] = Xb[(size_t)(k0 + kk) * HW + cc];
        }
#pragma unroll
        for (int i = 0; i < 16; i++) {
            int idx = tid + i * 256;
            int m = idx >> 5, kk = idx & 31;
            ws[m][kk] = W[(m0 + m) * CRn + k0 + kk];
        }
        __syncthreads();

#pragma unroll
        for (int kk = 0; kk < 32; kk++) {
            float a[8];
#pragma unroll
            for (int r = 0; r < 8; r++) a[r] = ws[rg * 8 + r][kk];
            float4 b0 = *(const float4*)&xs[kk][cg * 8];
            float4 b1 = *(const float4*)&xs[kk][cg * 8 + 4];
            float bb[8] = {b0.x, b0.y, b0.z, b0.w, b1.x, b1.y, b1.z, b1.w};
#pragma unroll
            for (int r = 0; r < 8; r++)
#pragma unroll
                for (int c = 0; c < 8; c++)
                    acc[r][c] = fmaf(a[r], bb[c], acc[r][c]);
        }
        __syncthreads();
    }

#pragma unroll
    for (int r = 0; r < 8; r++) {
        int row = m0 + rg * 8 + r;
        float bv = bias[row];
        float* Yp = OUT + (size_t)b * (DIMC * HW) + (size_t)row * HW + hw0 + cg * 8;
        float4 s0 = make_float4(acc[r][0] + bv, acc[r][1] + bv, acc[r][2] + bv, acc[r][3] + bv);
        float4 s1 = make_float4(acc[r][4] + bv, acc[r][5] + bv, acc[r][6] + bv, acc[r][7] + bv);
        *(float4*)(Yp)     = s0;
        *(float4*)(Yp + 4) = s1;
    }
}

// ---------------------------------------------------------------------------
// Launch. Inputs (metadata order — 13 inputs):
// 0:x 1:H22 2:W22 3:relative_pos_index 4:relative_coords_table
// 5:qkv_w 6:qkv_b 7:dep_conv_b 8:dep_conv1_w 9:dep_conv1_b
// 10:rpb_table 11:proj_w 12:proj_b
// ---------------------------------------------------------------------------
extern "C" void kernel_launch(void* const* d_in, const int* in_sizes, int n_in,
                              void* d_out, int out_size)
{
    const float* x      = (const float*)d_in[0];
    const float* qkv_w  = (const float*)d_in[5];
    const float* qkv_b  = (const float*)d_in[6];
    const float* dcb    = (const float*)d_in[7];
    const float* dc1w   = (const float*)d_in[8];
    const float* dc1b   = (const float*)d_in[9];
    const float* rpb    = (const float*)d_in[10];
    const float* proj_w = (const float*)d_in[11];
    const float* proj_b = (const float*)d_in[12];
    float* out = (float*)d_out;

    qkv_gemm_kernel<<<dim3(512, 2), 256>>>(x, qkv_w, qkv_b);
    attn_kernel<<<dim3(4, NHn, Bn), 256>>>(dc1w, dcb, dc1b, rpb);
    proj_gemm_kernel<<<dim3(512, 2), 256>>>(proj_w, proj_b, out);
}

// round 8
// speedup vs baseline: 3.4009x; 1.1657x over previous
#include <cuda_runtime.h>
#include <cuda_bf16.h>
#include <cstdint>

// Problem constants
#define Bn   16
#define HW   4096
#define IMG  64
#define DIMC 256
#define NHn  8
#define CPHn 8
#define QKVC 192
#define CRn  64
#define SCALE 0.17677669529663687f   // 32^-0.5

// Scratch
__device__ float g_qkv[(size_t)Bn * QKVC * HW];            // 50 MB fp32
__device__ float g_o64[(size_t)Bn * CRn * HW];             // 17 MB fp32
__device__ __nv_bfloat16 g_xhi[(size_t)Bn * DIMC * HW];    // 32 MB
__device__ __nv_bfloat16 g_xlo[(size_t)Bn * DIMC * HW];    // 32 MB

// ---------------------------------------------------------------------------
// mma.sync bf16 helper (valid on base sm_103 target; no tcgen05)
// ---------------------------------------------------------------------------
__device__ __forceinline__ void mma_bf16(float* c, const uint32_t* a, const uint32_t* b) {
    asm volatile(
        "mma.sync.aligned.m16n8k16.row.col.f32.bf16.bf16.f32 "
        "{%0,%1,%2,%3}, {%4,%5,%6,%7}, {%8,%9}, {%0,%1,%2,%3};"
        : "+f"(c[0]), "+f"(c[1]), "+f"(c[2]), "+f"(c[3])
        : "r"(a[0]), "r"(a[1]), "r"(a[2]), "r"(a[3]), "r"(b[0]), "r"(b[1]));
}

// ---------------------------------------------------------------------------
// Kernel 0: split X -> bf16 hi/lo (same [b][k][n] layout)
// ---------------------------------------------------------------------------
__global__ __launch_bounds__(256) void split_x_kernel(const float* __restrict__ X)
{
    size_t gid = (size_t)blockIdx.x * 256 + threadIdx.x;   // 4 floats each
    float4 v = ((const float4*)X)[gid];
    __nv_bfloat16 h0 = __float2bfloat16(v.x), h1 = __float2bfloat16(v.y);
    __nv_bfloat16 h2 = __float2bfloat16(v.z), h3 = __float2bfloat16(v.w);
    __nv_bfloat16 l0 = __float2bfloat16(v.x - __bfloat162float(h0));
    __nv_bfloat16 l1 = __float2bfloat16(v.y - __bfloat162float(h1));
    __nv_bfloat16 l2 = __float2bfloat16(v.z - __bfloat162float(h2));
    __nv_bfloat16 l3 = __float2bfloat16(v.w - __bfloat162float(h3));
    __nv_bfloat162 hA(h0, h1), hB(h2, h3), lA(l0, l1), lB(l2, l3);
    uint2 ho = make_uint2(*(uint32_t*)&hA, *(uint32_t*)&hB);
    uint2 lo = make_uint2(*(uint32_t*)&lA, *(uint32_t*)&lB);
    ((uint2*)g_xhi)[gid] = ho;
    ((uint2*)g_xlo)[gid] = lo;
}

// ---------------------------------------------------------------------------
// Kernel 1: QKV GEMM via mma.sync bf16-split.
// Y[b][m][n] = sum_k W[m][k] X[b][k][n] + bias[m]
// grid (512 n-tiles of 128, 3 m-tiles of 64); 256 threads = 8 warps (2M x 4N).
// Warp tile 32x32 = 2 mtiles(16) x 4 ntiles(8). K = 256; per k-chunk(32):
// sections hi*hi + lo*hi + hi*lo.
// A smem: W block [2(hi/lo)][64][256] bf16, row stride 264, resident.
// B smem: X chunk transposed [2][128 n][32 k] bf16, row stride 34.
// ---------------------------------------------------------------------------
#define AST 264
#define BST 34
#define A_ELE (2 * 64 * AST)     // 33792
#define B_ELE (2 * 128 * BST)    // 8704
#define QKV_SMEM ((A_ELE + B_ELE) * 2)   // 84992 bytes

__global__ __launch_bounds__(256) void qkv_mma_kernel(
    const float* __restrict__ W, const float* __restrict__ bias)
{
    extern __shared__ __nv_bfloat16 sm[];
    __nv_bfloat16* As = sm;            // [s][m][AST]
    __nv_bfloat16* Bs = sm + A_ELE;    // [s][n][BST]

    const int tid  = threadIdx.x;
    const int wid  = tid >> 5;
    const int lane = tid & 31;
    const int wm   = wid & 1;          // 0..1
    const int wn   = wid >> 1;         // 0..3
    const int g    = lane >> 2;        // 0..7
    const int tg   = lane & 3;         // 0..3

    const int m0g  = blockIdx.y * 64;
    const int col0 = blockIdx.x * 128;
    const int b    = col0 >> 12;
    const int nb   = col0 & 4095;

    // ---- load W block: 64 rows x 128 k-pairs, split hi/lo ----
#pragma unroll
    for (int i = 0; i < 32; i++) {
        int idx = tid + i * 256;       // 8192 pairs
        int m  = idx >> 7;
        int kp = idx & 127;
        float2 w = *(const float2*)(W + (size_t)(m0g + m) * DIMC + kp * 2);
        __nv_bfloat16 h0 = __float2bfloat16(w.x);
        __nv_bfloat16 h1 = __float2bfloat16(w.y);
        __nv_bfloat16 l0 = __float2bfloat16(w.x - __bfloat162float(h0));
        __nv_bfloat16 l1 = __float2bfloat16(w.y - __bfloat162float(h1));
        __nv_bfloat162 hh(h0, h1), ll(l0, l1);
        *(uint32_t*)&As[(size_t)m * AST + kp * 2]         = *(uint32_t*)&hh;
        *(uint32_t*)&As[(size_t)(64 + m) * AST + kp * 2]  = *(uint32_t*)&ll;   // lo block at m+64
    }

    const __nv_bfloat16* xh = g_xhi + ((size_t)b * DIMC) * HW + nb;
    const __nv_bfloat16* xl = g_xlo + ((size_t)b * DIMC) * HW + nb;

    float acc[2][4][4];
#pragma unroll
    for (int mt = 0; mt < 2; mt++)
#pragma unroll
        for (int nt = 0; nt < 4; nt++)
#pragma unroll
            for (int r = 0; r < 4; r++) acc[mt][nt][r] = 0.f;

    for (int kc = 0; kc < 8; kc++) {
        __syncthreads();   // Bs free (and covers As writes on first iter)
        // load B chunk: [2][32 k][128 n] -> transposed [2][n][k]
#pragma unroll
        for (int it = 0; it < 4; it++) {
            int idx = tid + it * 256;      // 1024 uint4 reads
            int s   = idx >> 9;
            int rem = idx & 511;
            int r   = rem >> 4;            // k row 0..31
            int q   = rem & 15;            // n group
            const __nv_bfloat16* sp = (s ? xl : xh) + (size_t)(kc * 32 + r) * HW + q * 8;
            uint4 v = *(const uint4*)sp;
            __nv_bfloat16 tmp[8];
            *(uint4*)tmp = v;
            __nv_bfloat16* bp = Bs + (size_t)s * 128 * BST + (q * 8) * BST + r;
#pragma unroll
            for (int i = 0; i < 8; i++) bp[i * BST] = tmp[i];
        }
        __syncthreads();

#pragma unroll
        for (int ks = 0; ks < 2; ks++) {
            const int kb = kc * 32 + ks * 16;   // column in As
            const int kbb = ks * 16;            // k in Bs chunk

            uint32_t ah[2][4], al[2][4];
#pragma unroll
            for (int mt = 0; mt < 2; mt++) {
                int row = wm * 32 + mt * 16;
                const __nv_bfloat16* a0 = As + (size_t)(row + g) * AST + kb + tg * 2;
                const __nv_bfloat16* a1 = As + (size_t)(row + g + 8) * AST + kb + tg * 2;
                ah[mt][0] = *(const uint32_t*)(a0);
                ah[mt][1] = *(const uint32_t*)(a1);
                ah[mt][2] = *(const uint32_t*)(a0 + 8);
                ah[mt][3] = *(const uint32_t*)(a1 + 8);
                al[mt][0] = *(const uint32_t*)(a0 + (size_t)64 * AST);
                al[mt][1] = *(const uint32_t*)(a1 + (size_t)64 * AST);
                al[mt][2] = *(const uint32_t*)(a0 + (size_t)64 * AST + 8);
                al[mt][3] = *(const uint32_t*)(a1 + (size_t)64 * AST + 8);
            }
            uint32_t bh[4][2], bl[4][2];
#pragma unroll
            for (int nt = 0; nt < 4; nt++) {
                int n = wn * 32 + nt * 8 + g;
                const __nv_bfloat16* b0 = Bs + (size_t)n * BST + kbb + tg * 2;
                bh[nt][0] = *(const uint32_t*)(b0);
                bh[nt][1] = *(const uint32_t*)(b0 + 8);
                bl[nt][0] = *(const uint32_t*)(b0 + (size_t)128 * BST);
                bl[nt][1] = *(const uint32_t*)(b0 + (size_t)128 * BST + 8);
            }
#pragma unroll
            for (int mt = 0; mt < 2; mt++)
#pragma unroll
                for (int nt = 0; nt < 4; nt++) {
                    mma_bf16(acc[mt][nt], ah[mt], bh[nt]);   // hi*hi
                    mma_bf16(acc[mt][nt], al[mt], bh[nt]);   // lo*hi
                    mma_bf16(acc[mt][nt], ah[mt], bl[nt]);   // hi*lo
                }
        }
    }

    // ---- epilogue: D(row, col), c0/c1 -> (g, 2tg..+1), c2/c3 -> (g+8, ..) ----
#pragma unroll
    for (int mt = 0; mt < 2; mt++) {
        int r0 = m0g + wm * 32 + mt * 16 + g;
        int r1 = r0 + 8;
        float bv0 = bias[r0], bv1 = bias[r1];
        float* d0 = g_qkv + (size_t)b * (QKVC * HW) + (size_t)r0 * HW + nb;
        float* d1 = g_qkv + (size_t)b * (QKVC * HW) + (size_t)r1 * HW + nb;
#pragma unroll
        for (int nt = 0; nt < 4; nt++) {
            int c = wn * 32 + nt * 8 + tg * 2;
            float2 v0 = make_float2(acc[mt][nt][0] + bv0, acc[mt][nt][1] + bv0);
            float2 v1 = make_float2(acc[mt][nt][2] + bv1, acc[mt][nt][3] + bv1);
            *(float2*)(d0 + c) = v0;
            *(float2*)(d1 + c) = v1;
        }
    }
}

// ---------------------------------------------------------------------------
// Kernel 2: fused unfold-conv + slide attention (unchanged from R5)
// ---------------------------------------------------------------------------
#define TS 32
#define HAL (TS + 2)
#define HALN (HAL * HAL)

__global__ __launch_bounds__(256) void attn_kernel(
    const float* __restrict__ w1g, const float* __restrict__ b0g,
    const float* __restrict__ b1g, const float* __restrict__ rpbg)
{
    __shared__ float hs[CPHn][HAL][HAL];
    __shared__ float w1p[72 * 12];
    __shared__ float rpb[9];

    const int tile = blockIdx.x;
    const int n    = blockIdx.y;
    const int b    = blockIdx.z;
    const int ty0  = (tile >> 1) * TS;
    const int tx0  = (tile & 1) * TS;
    const int tid  = threadIdx.x;
    const int tx   = tid & 31;
    const int tr   = tid >> 5;

    for (int i = tid; i < 648; i += 256) {
        int e = i / 9, t = i - e * 9;
        w1p[e * 12 + t] = w1g[i];
    }
    if (tid < 72) w1p[tid * 12 + 9] = b0g[tid] + b1g[tid];
    if (tid < 9)  rpb[tid] = rpbg[n * 9 + tid];

    const size_t hbase = (size_t)b * (QKVC * HW) + (size_t)(n * 24) * HW;
    const float* base_q = g_qkv + hbase;
    const float* base_k = g_qkv + hbase + (size_t)8  * HW;
    const float* base_v = g_qkv + hbase + (size_t)16 * HW;

    const int hw0 = (ty0 + tr * 4) * IMG + (tx0 + tx);

    float qv[CPHn][4];
    float qsum[4] = {0.f, 0.f, 0.f, 0.f};
#pragma unroll
    for (int g = 0; g < CPHn; g++) {
        const float* qp = base_q + (size_t)g * HW + hw0;
#pragma unroll
        for (int p = 0; p < 4; p++) {
            qv[g][p] = qp[p * IMG] * SCALE;
            qsum[p] += qv[g][p];
        }
    }

#pragma unroll
    for (int g = 0; g < CPHn; g++) {
        const float* src = base_k + (size_t)g * HW;
        for (int i = tid; i < HALN; i += 256) {
            int hy = i / HAL, hx = i - hy * HAL;
            int gy = ty0 - 1 + hy, gx = tx0 - 1 + hx;
            bool ok = (unsigned)gy < 64u && (unsigned)gx < 64u;
            ((float*)hs)[g * HALN + i] = ok ? src[gy * IMG + gx] : 0.f;
        }
    }
    __syncthreads();

    float lg[4][9];
#pragma unroll
    for (int p = 0; p < 4; p++)
#pragma unroll
        for (int j = 0; j < 9; j++) lg[p][j] = rpb[j] * qsum[p];

#pragma unroll
    for (int g = 0; g < CPHn; g++) {
        float t[6][3];
#pragma unroll
        for (int rr = 0; rr < 6; rr++)
#pragma unroll
            for (int cc = 0; cc < 3; cc++)
                t[rr][cc] = hs[g][tr * 4 + rr][tx + cc];
#pragma unroll
        for (int j = 0; j < 9; j++) {
            const int jh = j / 3, jw = j % 3;
            const int wb = (g * 9 + j) * 12;
            float4 wa = *(const float4*)&w1p[wb];
            float4 wc = *(const float4*)&w1p[wb + 4];
            float4 we = *(const float4*)&w1p[wb + 8];
#pragma unroll
            for (int p = 0; p < 4; p++) {
                float kj = t[p + jh][jw] + we.y;
                kj = fmaf(wa.x, t[p][0], kj);
                kj = fmaf(wa.y, t[p][1], kj);
                kj = fmaf(wa.z, t[p][2], kj);
                kj = fmaf(wa.w, t[p + 1][0], kj);
                kj = fmaf(wc.x, t[p + 1][1], kj);
                kj = fmaf(wc.y, t[p + 1][2], kj);
                kj = fmaf(wc.z, t[p + 2][0], kj);
                kj = fmaf(wc.w, t[p + 2][1], kj);
                kj = fmaf(we.x, t[p + 2][2], kj);
                lg[p][j] = fmaf(qv[g][p], kj, lg[p][j]);
            }
        }
    }

#pragma unroll
    for (int p = 0; p < 4; p++) {
        float mx = lg[p][0];
#pragma unroll
        for (int j = 1; j < 9; j++) mx = fmaxf(mx, lg[p][j]);
        float s = 0.f;
#pragma unroll
        for (int j = 0; j < 9; j++) { lg[p][j] = __expf(lg[p][j] - mx); s += lg[p][j]; }
        float inv = 1.f / s;
#pragma unroll
        for (int j = 0; j < 9; j++) lg[p][j] *= inv;
    }

    __syncthreads();
#pragma unroll
    for (int g = 0; g < CPHn; g++) {
        const float* src = base_v + (size_t)g * HW;
        for (int i = tid; i < HALN; i += 256) {
            int hy = i / HAL, hx = i - hy * HAL;
            int gy = ty0 - 1 + hy, gx = tx0 - 1 + hx;
            bool ok = (unsigned)gy < 64u && (unsigned)gx < 64u;
            ((float*)hs)[g * HALN + i] = ok ? src[gy * IMG + gx] : 0.f;
        }
    }
    __syncthreads();

    float* ob = g_o64 + (size_t)b * (CRn * HW) + (size_t)(n * CPHn) * HW + hw0;
#pragma unroll
    for (int g = 0; g < CPHn; g++) {
        float t[6][3];
#pragma unroll
        for (int rr = 0; rr < 6; rr++)
#pragma unroll
            for (int cc = 0; cc < 3; cc++)
                t[rr][cc] = hs[g][tr * 4 + rr][tx + cc];
        float og[4] = {0.f, 0.f, 0.f, 0.f};
#pragma unroll
        for (int j = 0; j < 9; j++) {
            const int jh = j / 3, jw = j % 3;
            const int wb = (g * 9 + j) * 12;
            float4 wa = *(const float4*)&w1p[wb];
            float4 wc = *(const float4*)&w1p[wb + 4];
            float4 we = *(const float4*)&w1p[wb + 8];
#pragma unroll
            for (int p = 0; p < 4; p++) {
                float vj = t[p + jh][jw] + we.y;
                vj = fmaf(wa.x, t[p][0], vj);
                vj = fmaf(wa.y, t[p][1], vj);
                vj = fmaf(wa.z, t[p][2], vj);
                vj = fmaf(wa.w, t[p + 1][0], vj);
                vj = fmaf(wc.x, t[p + 1][1], vj);
                vj = fmaf(wc.y, t[p + 1][2], vj);
                vj = fmaf(wc.z, t[p + 2][0], vj);
                vj = fmaf(wc.w, t[p + 2][1], vj);
                vj = fmaf(we.x, t[p + 2][2], vj);
                og[p] = fmaf(lg[p][j], vj, og[p]);
            }
        }
        float* op = ob + (size_t)g * HW;
#pragma unroll
        for (int p = 0; p < 4; p++) op[p * IMG] = og[p];
    }
}

// ---------------------------------------------------------------------------
// Kernel 3: projection GEMM (unchanged SIMT)
// ---------------------------------------------------------------------------
__global__ __launch_bounds__(256) void proj_gemm_kernel(
    const float* __restrict__ W, const float* __restrict__ bias,
    float* __restrict__ OUT)
{
    __shared__ float xs[32][128];
    __shared__ float ws[128][33];

    const int col0 = blockIdx.x * 128;
    const int b    = col0 >> 12;
    const int hw0  = col0 & 4095;
    const int m0   = blockIdx.y * 128;
    const int tid  = threadIdx.x;
    const int rg   = tid >> 4;
    const int cg   = tid & 15;

    const float* Xb = g_o64 + (size_t)b * (CRn * HW) + hw0;

    float acc[8][8];
#pragma unroll
    for (int r = 0; r < 8; r++)
#pragma unroll
        for (int c = 0; c < 8; c++) acc[r][c] = 0.f;

    for (int k0 = 0; k0 < CRn; k0 += 32) {
#pragma unroll
        for (int i = 0; i < 16; i++) {
            int idx = tid + i * 256;
            int kk = idx >> 7, cc = idx & 127;
            xs[kk][cc] = Xb[(size_t)(k0 + kk) * HW + cc];
        }
#pragma unroll
        for (int i = 0; i < 16; i++) {
            int idx = tid + i * 256;
            int m = idx >> 5, kk = idx & 31;
            ws[m][kk] = W[(m0 + m) * CRn + k0 + kk];
        }
        __syncthreads();

#pragma unroll
        for (int kk = 0; kk < 32; kk++) {
            float a[8];
#pragma unroll
            for (int r = 0; r < 8; r++) a[r] = ws[rg * 8 + r][kk];
            float4 b0 = *(const float4*)&xs[kk][cg * 8];
            float4 b1 = *(const float4*)&xs[kk][cg * 8 + 4];
            float bb[8] = {b0.x, b0.y, b0.z, b0.w, b1.x, b1.y, b1.z, b1.w};
#pragma unroll
            for (int r = 0; r < 8; r++)
#pragma unroll
                for (int c = 0; c < 8; c++)
                    acc[r][c] = fmaf(a[r], bb[c], acc[r][c]);
        }
        __syncthreads();
    }

#pragma unroll
    for (int r = 0; r < 8; r++) {
        int row = m0 + rg * 8 + r;
        float bv = bias[row];
        float* Yp = OUT + (size_t)b * (DIMC * HW) + (size_t)row * HW + hw0 + cg * 8;
        float4 s0 = make_float4(acc[r][0] + bv, acc[r][1] + bv, acc[r][2] + bv, acc[r][3] + bv);
        float4 s1 = make_float4(acc[r][4] + bv, acc[r][5] + bv, acc[r][6] + bv, acc[r][7] + bv);
        *(float4*)(Yp)     = s0;
        *(float4*)(Yp + 4) = s1;
    }
}

// ---------------------------------------------------------------------------
// Launch. Inputs: 0:x 1:H22 2:W22 3:rpi 4:rct 5:qkv_w 6:qkv_b 7:dep_conv_b
// 8:dep_conv1_w 9:dep_conv1_b 10:rpb_table 11:proj_w 12:proj_b
// ---------------------------------------------------------------------------
extern "C" void kernel_launch(void* const* d_in, const int* in_sizes, int n_in,
                              void* d_out, int out_size)
{
    const float* x      = (const float*)d_in[0];
    const float* qkv_w  = (const float*)d_in[5];
    const float* qkv_b  = (const float*)d_in[6];
    const float* dcb    = (const float*)d_in[7];
    const float* dc1w   = (const float*)d_in[8];
    const float* dc1b   = (const float*)d_in[9];
    const float* rpb    = (const float*)d_in[10];
    const float* proj_w = (const float*)d_in[11];
    const float* proj_b = (const float*)d_in[12];
    float* out = (float*)d_out;

    static int smem_set = 0;
    if (!smem_set) {
        cudaFuncSetAttribute(qkv_mma_kernel, cudaFuncAttributeMaxDynamicSharedMemorySize, QKV_SMEM);
        smem_set = 1;
    }

    split_x_kernel<<<16384, 256>>>(x);
    qkv_mma_kernel<<<dim3(512, 3), 256, QKV_SMEM>>>(qkv_w, qkv_b);
    attn_kernel<<<dim3(4, NHn, Bn), 256>>>(dc1w, dcb, dc1b, rpb);
    proj_gemm_kernel<<<dim3(512, 2), 256>>>(proj_w, proj_b, out);
}

// round 9
// speedup vs baseline: 3.7831x; 1.1124x over previous
#include <cuda_runtime.h>
#include <cuda_bf16.h>
#include <cstdint>

// Problem constants
#define Bn   16
#define HW   4096
#define IMG  64
#define DIMC 256
#define NHn  8
#define CPHn 8
#define QKVC 192
#define CRn  64
#define SCALE 0.17677669529663687f   // 32^-0.5

// Scratch
__device__ float g_qkv[(size_t)Bn * QKVC * HW];            // 50 MB fp32
__device__ __nv_bfloat16 g_xhi[(size_t)Bn * DIMC * HW];    // 32 MB
__device__ __nv_bfloat16 g_xlo[(size_t)Bn * DIMC * HW];    // 32 MB
__device__ __nv_bfloat16 g_ohi[(size_t)Bn * CRn * HW];     // 8 MB
__device__ __nv_bfloat16 g_olo[(size_t)Bn * CRn * HW];     // 8 MB

// ---------------------------------------------------------------------------
// mma.sync bf16 helper (valid on base sm_103 target)
// ---------------------------------------------------------------------------
__device__ __forceinline__ void mma_bf16(float* c, const uint32_t* a, const uint32_t* b) {
    asm volatile(
        "mma.sync.aligned.m16n8k16.row.col.f32.bf16.bf16.f32 "
        "{%0,%1,%2,%3}, {%4,%5,%6,%7}, {%8,%9}, {%0,%1,%2,%3};"
        : "+f"(c[0]), "+f"(c[1]), "+f"(c[2]), "+f"(c[3])
        : "r"(a[0]), "r"(a[1]), "r"(a[2]), "r"(a[3]), "r"(b[0]), "r"(b[1]));
}

// ---------------------------------------------------------------------------
// Kernel 0: split X -> bf16 hi/lo (same [b][k][n] layout)
// ---------------------------------------------------------------------------
__global__ __launch_bounds__(256) void split_x_kernel(const float* __restrict__ X)
{
    size_t gid = (size_t)blockIdx.x * 256 + threadIdx.x;
    float4 v = ((const float4*)X)[gid];
    __nv_bfloat16 h0 = __float2bfloat16(v.x), h1 = __float2bfloat16(v.y);
    __nv_bfloat16 h2 = __float2bfloat16(v.z), h3 = __float2bfloat16(v.w);
    __nv_bfloat16 l0 = __float2bfloat16(v.x - __bfloat162float(h0));
    __nv_bfloat16 l1 = __float2bfloat16(v.y - __bfloat162float(h1));
    __nv_bfloat16 l2 = __float2bfloat16(v.z - __bfloat162float(h2));
    __nv_bfloat16 l3 = __float2bfloat16(v.w - __bfloat162float(h3));
    __nv_bfloat162 hA(h0, h1), hB(h2, h3), lA(l0, l1), lB(l2, l3);
    uint2 ho = make_uint2(*(uint32_t*)&hA, *(uint32_t*)&hB);
    uint2 lo = make_uint2(*(uint32_t*)&lA, *(uint32_t*)&lB);
    ((uint2*)g_xhi)[gid] = ho;
    ((uint2*)g_xlo)[gid] = lo;
}

// ---------------------------------------------------------------------------
// Kernel 1: QKV GEMM via mma.sync bf16-split (unchanged from R8)
// ---------------------------------------------------------------------------
#define AST 264
#define BST 34
#define A_ELE (2 * 64 * AST)
#define B_ELE (2 * 128 * BST)
#define QKV_SMEM ((A_ELE + B_ELE) * 2)

__global__ __launch_bounds__(256) void qkv_mma_kernel(
    const float* __restrict__ W, const float* __restrict__ bias)
{
    extern __shared__ __nv_bfloat16 sm[];
    __nv_bfloat16* As = sm;
    __nv_bfloat16* Bs = sm + A_ELE;

    const int tid  = threadIdx.x;
    const int wid  = tid >> 5;
    const int lane = tid & 31;
    const int wm   = wid & 1;
    const int wn   = wid >> 1;
    const int g    = lane >> 2;
    const int tg   = lane & 3;

    const int m0g  = blockIdx.y * 64;
    const int col0 = blockIdx.x * 128;
    const int b    = col0 >> 12;
    const int nb   = col0 & 4095;

#pragma unroll
    for (int i = 0; i < 32; i++) {
        int idx = tid + i * 256;
        int m  = idx >> 7;
        int kp = idx & 127;
        float2 w = *(const float2*)(W + (size_t)(m0g + m) * DIMC + kp * 2);
        __nv_bfloat16 h0 = __float2bfloat16(w.x);
        __nv_bfloat16 h1 = __float2bfloat16(w.y);
        __nv_bfloat16 l0 = __float2bfloat16(w.x - __bfloat162float(h0));
        __nv_bfloat16 l1 = __float2bfloat16(w.y - __bfloat162float(h1));
        __nv_bfloat162 hh(h0, h1), ll(l0, l1);
        *(uint32_t*)&As[(size_t)m * AST + kp * 2]        = *(uint32_t*)&hh;
        *(uint32_t*)&As[(size_t)(64 + m) * AST + kp * 2] = *(uint32_t*)&ll;
    }

    const __nv_bfloat16* xh = g_xhi + ((size_t)b * DIMC) * HW + nb;
    const __nv_bfloat16* xl = g_xlo + ((size_t)b * DIMC) * HW + nb;

    float acc[2][4][4];
#pragma unroll
    for (int mt = 0; mt < 2; mt++)
#pragma unroll
        for (int nt = 0; nt < 4; nt++)
#pragma unroll
            for (int r = 0; r < 4; r++) acc[mt][nt][r] = 0.f;

    for (int kc = 0; kc < 8; kc++) {
        __syncthreads();
#pragma unroll
        for (int it = 0; it < 4; it++) {
            int idx = tid + it * 256;
            int s   = idx >> 9;
            int rem = idx & 511;
            int r   = rem >> 4;
            int q   = rem & 15;
            const __nv_bfloat16* sp = (s ? xl : xh) + (size_t)(kc * 32 + r) * HW + q * 8;
            uint4 v = *(const uint4*)sp;
            __nv_bfloat16 tmp[8];
            *(uint4*)tmp = v;
            __nv_bfloat16* bp = Bs + (size_t)s * 128 * BST + (q * 8) * BST + r;
#pragma unroll
            for (int i = 0; i < 8; i++) bp[i * BST] = tmp[i];
        }
        __syncthreads();

#pragma unroll
        for (int ks = 0; ks < 2; ks++) {
            const int kb = kc * 32 + ks * 16;
            const int kbb = ks * 16;

            uint32_t ah[2][4], al[2][4];
#pragma unroll
            for (int mt = 0; mt < 2; mt++) {
                int row = wm * 32 + mt * 16;
                const __nv_bfloat16* a0 = As + (size_t)(row + g) * AST + kb + tg * 2;
                const __nv_bfloat16* a1 = As + (size_t)(row + g + 8) * AST + kb + tg * 2;
                ah[mt][0] = *(const uint32_t*)(a0);
                ah[mt][1] = *(const uint32_t*)(a1);
                ah[mt][2] = *(const uint32_t*)(a0 + 8);
                ah[mt][3] = *(const uint32_t*)(a1 + 8);
                al[mt][0] = *(const uint32_t*)(a0 + (size_t)64 * AST);
                al[mt][1] = *(const uint32_t*)(a1 + (size_t)64 * AST);
                al[mt][2] = *(const uint32_t*)(a0 + (size_t)64 * AST + 8);
                al[mt][3] = *(const uint32_t*)(a1 + (size_t)64 * AST + 8);
            }
            uint32_t bh[4][2], bl[4][2];
#pragma unroll
            for (int nt = 0; nt < 4; nt++) {
                int n = wn * 32 + nt * 8 + g;
                const __nv_bfloat16* b0 = Bs + (size_t)n * BST + kbb + tg * 2;
                bh[nt][0] = *(const uint32_t*)(b0);
                bh[nt][1] = *(const uint32_t*)(b0 + 8);
                bl[nt][0] = *(const uint32_t*)(b0 + (size_t)128 * BST);
                bl[nt][1] = *(const uint32_t*)(b0 + (size_t)128 * BST + 8);
            }
#pragma unroll
            for (int mt = 0; mt < 2; mt++)
#pragma unroll
                for (int nt = 0; nt < 4; nt++) {
                    mma_bf16(acc[mt][nt], ah[mt], bh[nt]);
                    mma_bf16(acc[mt][nt], al[mt], bh[nt]);
                    mma_bf16(acc[mt][nt], ah[mt], bl[nt]);
                }
        }
    }

#pragma unroll
    for (int mt = 0; mt < 2; mt++) {
        int r0 = m0g + wm * 32 + mt * 16 + g;
        int r1 = r0 + 8;
        float bv0 = bias[r0], bv1 = bias[r1];
        float* d0 = g_qkv + (size_t)b * (QKVC * HW) + (size_t)r0 * HW + nb;
        float* d1 = g_qkv + (size_t)b * (QKVC * HW) + (size_t)r1 * HW + nb;
#pragma unroll
        for (int nt = 0; nt < 4; nt++) {
            int c = wn * 32 + nt * 8 + tg * 2;
            float2 v0 = make_float2(acc[mt][nt][0] + bv0, acc[mt][nt][1] + bv0);
            float2 v1 = make_float2(acc[mt][nt][2] + bv1, acc[mt][nt][3] + bv1);
            *(float2*)(d0 + c) = v0;
            *(float2*)(d1 + c) = v1;
        }
    }
}

// ---------------------------------------------------------------------------
// Kernel 2: fused unfold-conv + slide attention.
// Identical math to R5, but output written as bf16 hi/lo pair (for proj mma).
// ---------------------------------------------------------------------------
#define TS 32
#define HAL (TS + 2)
#define HALN (HAL * HAL)

__global__ __launch_bounds__(256) void attn_kernel(
    const float* __restrict__ w1g, const float* __restrict__ b0g,
    const float* __restrict__ b1g, const float* __restrict__ rpbg)
{
    __shared__ float hs[CPHn][HAL][HAL];
    __shared__ float w1p[72 * 12];
    __shared__ float rpb[9];

    const int tile = blockIdx.x;
    const int n    = blockIdx.y;
    const int b    = blockIdx.z;
    const int ty0  = (tile >> 1) * TS;
    const int tx0  = (tile & 1) * TS;
    const int tid  = threadIdx.x;
    const int tx   = tid & 31;
    const int tr   = tid >> 5;

    for (int i = tid; i < 648; i += 256) {
        int e = i / 9, t = i - e * 9;
        w1p[e * 12 + t] = w1g[i];
    }
    if (tid < 72) w1p[tid * 12 + 9] = b0g[tid] + b1g[tid];
    if (tid < 9)  rpb[tid] = rpbg[n * 9 + tid];

    const size_t hbase = (size_t)b * (QKVC * HW) + (size_t)(n * 24) * HW;
    const float* base_q = g_qkv + hbase;
    const float* base_k = g_qkv + hbase + (size_t)8  * HW;
    const float* base_v = g_qkv + hbase + (size_t)16 * HW;

    const int hw0 = (ty0 + tr * 4) * IMG + (tx0 + tx);

    float qv[CPHn][4];
    float qsum[4] = {0.f, 0.f, 0.f, 0.f};
#pragma unroll
    for (int g = 0; g < CPHn; g++) {
        const float* qp = base_q + (size_t)g * HW + hw0;
#pragma unroll
        for (int p = 0; p < 4; p++) {
            qv[g][p] = qp[p * IMG] * SCALE;
            qsum[p] += qv[g][p];
        }
    }

#pragma unroll
    for (int g = 0; g < CPHn; g++) {
        const float* src = base_k + (size_t)g * HW;
        for (int i = tid; i < HALN; i += 256) {
            int hy = i / HAL, hx = i - hy * HAL;
            int gy = ty0 - 1 + hy, gx = tx0 - 1 + hx;
            bool ok = (unsigned)gy < 64u && (unsigned)gx < 64u;
            ((float*)hs)[g * HALN + i] = ok ? src[gy * IMG + gx] : 0.f;
        }
    }
    __syncthreads();

    float lg[4][9];
#pragma unroll
    for (int p = 0; p < 4; p++)
#pragma unroll
        for (int j = 0; j < 9; j++) lg[p][j] = rpb[j] * qsum[p];

#pragma unroll
    for (int g = 0; g < CPHn; g++) {
        float t[6][3];
#pragma unroll
        for (int rr = 0; rr < 6; rr++)
#pragma unroll
            for (int cc = 0; cc < 3; cc++)
                t[rr][cc] = hs[g][tr * 4 + rr][tx + cc];
#pragma unroll
        for (int j = 0; j < 9; j++) {
            const int jh = j / 3, jw = j % 3;
            const int wb = (g * 9 + j) * 12;
            float4 wa = *(const float4*)&w1p[wb];
            float4 wc = *(const float4*)&w1p[wb + 4];
            float4 we = *(const float4*)&w1p[wb + 8];
#pragma unroll
            for (int p = 0; p < 4; p++) {
                float kj = t[p + jh][jw] + we.y;
                kj = fmaf(wa.x, t[p][0], kj);
                kj = fmaf(wa.y, t[p][1], kj);
                kj = fmaf(wa.z, t[p][2], kj);
                kj = fmaf(wa.w, t[p + 1][0], kj);
                kj = fmaf(wc.x, t[p + 1][1], kj);
                kj = fmaf(wc.y, t[p + 1][2], kj);
                kj = fmaf(wc.z, t[p + 2][0], kj);
                kj = fmaf(wc.w, t[p + 2][1], kj);
                kj = fmaf(we.x, t[p + 2][2], kj);
                lg[p][j] = fmaf(qv[g][p], kj, lg[p][j]);
            }
        }
    }

#pragma unroll
    for (int p = 0; p < 4; p++) {
        float mx = lg[p][0];
#pragma unroll
        for (int j = 1; j < 9; j++) mx = fmaxf(mx, lg[p][j]);
        float s = 0.f;
#pragma unroll
        for (int j = 0; j < 9; j++) { lg[p][j] = __expf(lg[p][j] - mx); s += lg[p][j]; }
        float inv = 1.f / s;
#pragma unroll
        for (int j = 0; j < 9; j++) lg[p][j] *= inv;
    }

    __syncthreads();
#pragma unroll
    for (int g = 0; g < CPHn; g++) {
        const float* src = base_v + (size_t)g * HW;
        for (int i = tid; i < HALN; i += 256) {
            int hy = i / HAL, hx = i - hy * HAL;
            int gy = ty0 - 1 + hy, gx = tx0 - 1 + hx;
            bool ok = (unsigned)gy < 64u && (unsigned)gx < 64u;
            ((float*)hs)[g * HALN + i] = ok ? src[gy * IMG + gx] : 0.f;
        }
    }
    __syncthreads();

    const size_t obase = (size_t)b * (CRn * HW) + (size_t)(n * CPHn) * HW + hw0;
#pragma unroll
    for (int g = 0; g < CPHn; g++) {
        float t[6][3];
#pragma unroll
        for (int rr = 0; rr < 6; rr++)
#pragma unroll
            for (int cc = 0; cc < 3; cc++)
                t[rr][cc] = hs[g][tr * 4 + rr][tx + cc];
        float og[4] = {0.f, 0.f, 0.f, 0.f};
#pragma unroll
        for (int j = 0; j < 9; j++) {
            const int jh = j / 3, jw = j % 3;
            const int wb = (g * 9 + j) * 12;
            float4 wa = *(const float4*)&w1p[wb];
            float4 wc = *(const float4*)&w1p[wb + 4];
            float4 we = *(const float4*)&w1p[wb + 8];
#pragma unroll
            for (int p = 0; p < 4; p++) {
                float vj = t[p + jh][jw] + we.y;
                vj = fmaf(wa.x, t[p][0], vj);
                vj = fmaf(wa.y, t[p][1], vj);
                vj = fmaf(wa.z, t[p][2], vj);
                vj = fmaf(wa.w, t[p + 1][0], vj);
                vj = fmaf(wc.x, t[p + 1][1], vj);
                vj = fmaf(wc.y, t[p + 1][2], vj);
                vj = fmaf(wc.z, t[p + 2][0], vj);
                vj = fmaf(wc.w, t[p + 2][1], vj);
                vj = fmaf(we.x, t[p + 2][2], vj);
                og[p] = fmaf(lg[p][j], vj, og[p]);
            }
        }
        __nv_bfloat16* oph = g_ohi + obase + (size_t)g * HW;
        __nv_bfloat16* opl = g_olo + obase + (size_t)g * HW;
#pragma unroll
        for (int p = 0; p < 4; p++) {
            __nv_bfloat16 h = __float2bfloat16(og[p]);
            __nv_bfloat16 l = __float2bfloat16(og[p] - __bfloat162float(h));
            oph[p * IMG] = h;
            opl[p * IMG] = l;
        }
    }
}

// ---------------------------------------------------------------------------
// Kernel 3: projection GEMM via mma.sync bf16-split.
// OUT[b][m][n] = sum_k Wp[m][k] O[b][k][n] + pb[m];  M=256, K=64.
// grid (512 n-tiles of 128, 4 m-tiles of 64); same warp layout as qkv_mma.
// ---------------------------------------------------------------------------
#define AST2 72
#define A2_ELE (2 * 64 * AST2)     // 9216
#define B2_ELE (2 * 128 * BST)     // 8704
#define PROJ_SMEM ((A2_ELE + B2_ELE) * 2)   // 35840 bytes

__global__ __launch_bounds__(256) void proj_mma_kernel(
    const float* __restrict__ W, const float* __restrict__ bias,
    float* __restrict__ OUT)
{
    extern __shared__ __nv_bfloat16 sm2[];
    __nv_bfloat16* As = sm2;             // [s][64][AST2]
    __nv_bfloat16* Bs = sm2 + A2_ELE;    // [s][128][BST]

    const int tid  = threadIdx.x;
    const int wid  = tid >> 5;
    const int lane = tid & 31;
    const int wm   = wid & 1;
    const int wn   = wid >> 1;
    const int g    = lane >> 2;
    const int tg   = lane & 3;

    const int m0g  = blockIdx.y * 64;
    const int col0 = blockIdx.x * 128;
    const int b    = col0 >> 12;
    const int nb   = col0 & 4095;

    // ---- load W block: 64 rows x 32 k-pairs, split hi/lo ----
#pragma unroll
    for (int i = 0; i < 8; i++) {
        int idx = tid + i * 256;       // 2048 pairs
        int m  = idx >> 5;
        int kp = idx & 31;
        float2 w = *(const float2*)(W + (size_t)(m0g + m) * CRn + kp * 2);
        __nv_bfloat16 h0 = __float2bfloat16(w.x);
        __nv_bfloat16 h1 = __float2bfloat16(w.y);
        __nv_bfloat16 l0 = __float2bfloat16(w.x - __bfloat162float(h0));
        __nv_bfloat16 l1 = __float2bfloat16(w.y - __bfloat162float(h1));
        __nv_bfloat162 hh(h0, h1), ll(l0, l1);
        *(uint32_t*)&As[(size_t)m * AST2 + kp * 2]        = *(uint32_t*)&hh;
        *(uint32_t*)&As[(size_t)(64 + m) * AST2 + kp * 2] = *(uint32_t*)&ll;
    }

    const __nv_bfloat16* xh = g_ohi + ((size_t)b * CRn) * HW + nb;
    const __nv_bfloat16* xl = g_olo + ((size_t)b * CRn) * HW + nb;

    float acc[2][4][4];
#pragma unroll
    for (int mt = 0; mt < 2; mt++)
#pragma unroll
        for (int nt = 0; nt < 4; nt++)
#pragma unroll
            for (int r = 0; r < 4; r++) acc[mt][nt][r] = 0.f;

    for (int kc = 0; kc < 2; kc++) {
        __syncthreads();
#pragma unroll
        for (int it = 0; it < 4; it++) {
            int idx = tid + it * 256;
            int s   = idx >> 9;
            int rem = idx & 511;
            int r   = rem >> 4;
            int q   = rem & 15;
            const __nv_bfloat16* sp = (s ? xl : xh) + (size_t)(kc * 32 + r) * HW + q * 8;
            uint4 v = *(const uint4*)sp;
            __nv_bfloat16 tmp[8];
            *(uint4*)tmp = v;
            __nv_bfloat16* bp = Bs + (size_t)s * 128 * BST + (q * 8) * BST + r;
#pragma unroll
            for (int i = 0; i < 8; i++) bp[i * BST] = tmp[i];
        }
        __syncthreads();

#pragma unroll
        for (int ks = 0; ks < 2; ks++) {
            const int kb = kc * 32 + ks * 16;   // As column (K=64)
            const int kbb = ks * 16;

            uint32_t ah[2][4], al[2][4];
#pragma unroll
            for (int mt = 0; mt < 2; mt++) {
                int row = wm * 32 + mt * 16;
                const __nv_bfloat16* a0 = As + (size_t)(row + g) * AST2 + kb + tg * 2;
                const __nv_bfloat16* a1 = As + (size_t)(row + g + 8) * AST2 + kb + tg * 2;
                ah[mt][0] = *(const uint32_t*)(a0);
                ah[mt][1] = *(const uint32_t*)(a1);
                ah[mt][2] = *(const uint32_t*)(a0 + 8);
                ah[mt][3] = *(const uint32_t*)(a1 + 8);
                al[mt][0] = *(const uint32_t*)(a0 + (size_t)64 * AST2);
                al[mt][1] = *(const uint32_t*)(a1 + (size_t)64 * AST2);
                al[mt][2] = *(const uint32_t*)(a0 + (size_t)64 * AST2 + 8);
                al[mt][3] = *(const uint32_t*)(a1 + (size_t)64 * AST2 + 8);
            }
            uint32_t bh[4][2], bl[4][2];
#pragma unroll
            for (int nt = 0; nt < 4; nt++) {
                int n = wn * 32 + nt * 8 + g;
                const __nv_bfloat16* b0 = Bs + (size_t)n * BST + kbb + tg * 2;
                bh[nt][0] = *(const uint32_t*)(b0);
                bh[nt][1] = *(const uint32_t*)(b0 + 8);
                bl[nt][0] = *(const uint32_t*)(b0 + (size_t)128 * BST);
                bl[nt][1] = *(const uint32_t*)(b0 + (size_t)128 * BST + 8);
            }
#pragma unroll
            for (int mt = 0; mt < 2; mt++)
#pragma unroll
                for (int nt = 0; nt < 4; nt++) {
                    mma_bf16(acc[mt][nt], ah[mt], bh[nt]);
                    mma_bf16(acc[mt][nt], al[mt], bh[nt]);
                    mma_bf16(acc[mt][nt], ah[mt], bl[nt]);
                }
        }
    }

#pragma unroll
    for (int mt = 0; mt < 2; mt++) {
        int r0 = m0g + wm * 32 + mt * 16 + g;
        int r1 = r0 + 8;
        float bv0 = bias[r0], bv1 = bias[r1];
        float* d0 = OUT + (size_t)b * (DIMC * HW) + (size_t)r0 * HW + nb;
        float* d1 = OUT + (size_t)b * (DIMC * HW) + (size_t)r1 * HW + nb;
#pragma unroll
        for (int nt = 0; nt < 4; nt++) {
            int c = wn * 32 + nt * 8 + tg * 2;
            float2 v0 = make_float2(acc[mt][nt][0] + bv0, acc[mt][nt][1] + bv0);
            float2 v1 = make_float2(acc[mt][nt][2] + bv1, acc[mt][nt][3] + bv1);
            *(float2*)(d0 + c) = v0;
            *(float2*)(d1 + c) = v1;
        }
    }
}

// ---------------------------------------------------------------------------
// Launch. Inputs: 0:x 1:H22 2:W22 3:rpi 4:rct 5:qkv_w 6:qkv_b 7:dep_conv_b
// 8:dep_conv1_w 9:dep_conv1_b 10:rpb_table 11:proj_w 12:proj_b
// ---------------------------------------------------------------------------
extern "C" void kernel_launch(void* const* d_in, const int* in_sizes, int n_in,
                              void* d_out, int out_size)
{
    const float* x      = (const float*)d_in[0];
    const float* qkv_w  = (const float*)d_in[5];
    const float* qkv_b  = (const float*)d_in[6];
    const float* dcb    = (const float*)d_in[7];
    const float* dc1w   = (const float*)d_in[8];
    const float* dc1b   = (const float*)d_in[9];
    const float* rpb    = (const float*)d_in[10];
    const float* proj_w = (const float*)d_in[11];
    const float* proj_b = (const float*)d_in[12];
    float* out = (float*)d_out;

    static int smem_set = 0;
    if (!smem_set) {
        cudaFuncSetAttribute(qkv_mma_kernel, cudaFuncAttributeMaxDynamicSharedMemorySize, QKV_SMEM);
        cudaFuncSetAttribute(proj_mma_kernel, cudaFuncAttributeMaxDynamicSharedMemorySize, PROJ_SMEM);
        smem_set = 1;
    }

    split_x_kernel<<<16384, 256>>>(x);
    qkv_mma_kernel<<<dim3(512, 3), 256, QKV_SMEM>>>(qkv_w, qkv_b);
    attn_kernel<<<dim3(4, NHn, Bn), 256>>>(dcb ? dc1w : dc1w, dcb, dc1b, rpb);
    proj_mma_kernel<<<dim3(512, 4), 256, PROJ_SMEM>>>(proj_w, proj_b, out);
}

// round 10
// speedup vs baseline: 4.9809x; 1.3166x over previous
#include <cuda_runtime.h>
#include <cuda_bf16.h>
#include <cstdint>

// Problem constants
#define Bn   16
#define HW   4096
#define IMG  64
#define DIMC 256
#define NHn  8
#define CPHn 8
#define QKVC 192
#define CRn  64
#define SCALE 0.17677669529663687f   // 32^-0.5

// Scratch
__device__ float g_qkv[(size_t)Bn * QKVC * HW];            // 50 MB fp32
__device__ __nv_bfloat16 g_xhi[(size_t)Bn * DIMC * HW];    // 32 MB
__device__ __nv_bfloat16 g_xlo[(size_t)Bn * DIMC * HW];    // 32 MB
__device__ __nv_bfloat16 g_ohi[(size_t)Bn * CRn * HW];     // 8 MB
__device__ __nv_bfloat16 g_olo[(size_t)Bn * CRn * HW];     // 8 MB

// ---------------------------------------------------------------------------
// PTX helpers (all base-sm_103-legal: mma.sync, ldmatrix, cp.async)
// ---------------------------------------------------------------------------
__device__ __forceinline__ void mma_bf16(float* c, const uint32_t* a, const uint32_t* b) {
    asm volatile(
        "mma.sync.aligned.m16n8k16.row.col.f32.bf16.bf16.f32 "
        "{%0,%1,%2,%3}, {%4,%5,%6,%7}, {%8,%9}, {%0,%1,%2,%3};"
        : "+f"(c[0]), "+f"(c[1]), "+f"(c[2]), "+f"(c[3])
        : "r"(a[0]), "r"(a[1]), "r"(a[2]), "r"(a[3]), "r"(b[0]), "r"(b[1]));
}
__device__ __forceinline__ void ldm_x4(uint32_t* r, uint32_t addr) {
    asm volatile("ldmatrix.sync.aligned.m8n8.x4.shared.b16 {%0,%1,%2,%3}, [%4];"
        : "=r"(r[0]), "=r"(r[1]), "=r"(r[2]), "=r"(r[3]) : "r"(addr));
}
__device__ __forceinline__ void ldm_x4_t(uint32_t* r, uint32_t addr) {
    asm volatile("ldmatrix.sync.aligned.m8n8.x4.trans.shared.b16 {%0,%1,%2,%3}, [%4];"
        : "=r"(r[0]), "=r"(r[1]), "=r"(r[2]), "=r"(r[3]) : "r"(addr));
}
__device__ __forceinline__ void cp16(uint32_t dst, const void* src) {
    asm volatile("cp.async.cg.shared.global [%0], [%1], 16;" :: "r"(dst), "l"(src));
}
#define CP_COMMIT() asm volatile("cp.async.commit_group;" ::: "memory")
#define CP_WAIT0()  asm volatile("cp.async.wait_group 0;" ::: "memory")

// ---------------------------------------------------------------------------
// Kernel 0: split X -> bf16 hi/lo
// ---------------------------------------------------------------------------
__global__ __launch_bounds__(256) void split_x_kernel(const float* __restrict__ X)
{
    size_t gid = (size_t)blockIdx.x * 256 + threadIdx.x;
    float4 v = ((const float4*)X)[gid];
    __nv_bfloat16 h0 = __float2bfloat16(v.x), h1 = __float2bfloat16(v.y);
    __nv_bfloat16 h2 = __float2bfloat16(v.z), h3 = __float2bfloat16(v.w);
    __nv_bfloat16 l0 = __float2bfloat16(v.x - __bfloat162float(h0));
    __nv_bfloat16 l1 = __float2bfloat16(v.y - __bfloat162float(h1));
    __nv_bfloat16 l2 = __float2bfloat16(v.z - __bfloat162float(h2));
    __nv_bfloat16 l3 = __float2bfloat16(v.w - __bfloat162float(h3));
    __nv_bfloat162 hA(h0, h1), hB(h2, h3), lA(l0, l1), lB(l2, l3);
    ((uint2*)g_xhi)[gid] = make_uint2(*(uint32_t*)&hA, *(uint32_t*)&hB);
    ((uint2*)g_xlo)[gid] = make_uint2(*(uint32_t*)&lA, *(uint32_t*)&lB);
}

// ---------------------------------------------------------------------------
// Kernel 1: QKV GEMM (mma.sync bf16-split, ldmatrix + cp.async double-buffer)
// Block tile 64M x 128N, 8 warps (2Mx4N), K=256 in 8 chunks of 32.
// A smem: [hi/lo rows][64][AST] bf16, resident. B smem: [2 buf][2 s][32 k][136 n].
// ---------------------------------------------------------------------------
#define AST   264
#define AROWB (AST * 2)          // 528 bytes
#define A_ELE (2 * 64 * AST)     // elements
#define BSTn  136
#define BROWB (BSTn * 2)         // 272 bytes
#define BCHUNKB (32 * BROWB)     // 8704 bytes per s
#define BBUFB   (2 * BCHUNKB)    // 17408 bytes per buffer
#define QKV_SMEM (A_ELE * 2 + 2 * BBUFB)   // 67584 + 34816 = 102400

__global__ __launch_bounds__(256) void qkv_mma_kernel(
    const float* __restrict__ W, const float* __restrict__ bias)
{
    extern __shared__ __nv_bfloat16 sm[];
    __nv_bfloat16* As = sm;
    __nv_bfloat16* Bs = sm + A_ELE;

    const int tid  = threadIdx.x;
    const int wid  = tid >> 5;
    const int lane = tid & 31;
    const int wm   = wid & 1;
    const int wn   = wid >> 1;
    const int g    = lane >> 2;
    const int tg   = lane & 3;

    const int m0g  = blockIdx.y * 64;
    const int col0 = blockIdx.x * 128;
    const int b    = col0 >> 12;
    const int nb   = col0 & 4095;

    const __nv_bfloat16* xh = g_xhi + ((size_t)b * DIMC) * HW + nb;
    const __nv_bfloat16* xl = g_xlo + ((size_t)b * DIMC) * HW + nb;

    const uint32_t bs_b = (uint32_t)__cvta_generic_to_shared(Bs);

    // ---- prefetch B chunk 0 into buffer 0 ----
    {
        const int s = tid >> 9, rem = tid & 511;   // tid<512 handled by it-loop
#pragma unroll
        for (int it = 0; it < 4; it++) {
            int idx = tid + it * 256;
            int ss = idx >> 9, r = (idx >> 4) & 31, q = idx & 15;
            const __nv_bfloat16* src = (ss ? xl : xh) + (size_t)r * HW + q * 8;
            cp16(bs_b + ss * BCHUNKB + r * BROWB + q * 16, src);
        }
        (void)s; (void)rem;
    }
    CP_COMMIT();

    // ---- load A (W block, split hi/lo) ----
#pragma unroll
    for (int i = 0; i < 32; i++) {
        int idx = tid + i * 256;
        int m  = idx >> 7;
        int kp = idx & 127;
        float2 w = *(const float2*)(W + (size_t)(m0g + m) * DIMC + kp * 2);
        __nv_bfloat16 h0 = __float2bfloat16(w.x);
        __nv_bfloat16 h1 = __float2bfloat16(w.y);
        __nv_bfloat16 l0 = __float2bfloat16(w.x - __bfloat162float(h0));
        __nv_bfloat16 l1 = __float2bfloat16(w.y - __bfloat162float(h1));
        __nv_bfloat162 hh(h0, h1), ll(l0, l1);
        *(uint32_t*)&As[(size_t)m * AST + kp * 2]        = *(uint32_t*)&hh;
        *(uint32_t*)&As[(size_t)(64 + m) * AST + kp * 2] = *(uint32_t*)&ll;
    }

    // per-lane ldmatrix bases (byte addresses)
    const uint32_t a_lane = (uint32_t)__cvta_generic_to_shared(As)
                          + (lane & 15) * AROWB + (lane >> 4) * 16;
    const uint32_t b_lane = bs_b + (lane & 15) * BROWB + (lane >> 4) * 16;

    float acc[2][4][4];
#pragma unroll
    for (int mt = 0; mt < 2; mt++)
#pragma unroll
        for (int nt = 0; nt < 4; nt++)
#pragma unroll
            for (int r = 0; r < 4; r++) acc[mt][nt][r] = 0.f;

    for (int kc = 0; kc < 8; kc++) {
        const int buf = kc & 1;
        CP_WAIT0();
        __syncthreads();

        if (kc < 7) {
#pragma unroll
            for (int it = 0; it < 4; it++) {
                int idx = tid + it * 256;
                int ss = idx >> 9, r = (idx >> 4) & 31, q = idx & 15;
                const __nv_bfloat16* src = (ss ? xl : xh) + (size_t)((kc + 1) * 32 + r) * HW + q * 8;
                cp16(bs_b + (buf ^ 1) * BBUFB + ss * BCHUNKB + r * BROWB + q * 16, src);
            }
            CP_COMMIT();
        }

#pragma unroll
        for (int ks = 0; ks < 2; ks++) {
            const int k0 = kc * 32 + ks * 16;    // A column
            uint32_t ah[2][4], al[2][4];
#pragma unroll
            for (int mt = 0; mt < 2; mt++) {
                uint32_t a0 = a_lane + (wm * 32 + mt * 16) * AROWB + k0 * 2;
                ldm_x4(ah[mt], a0);
                ldm_x4(al[mt], a0 + 64 * AROWB);
            }
            uint32_t bh[2][4], bl[2][4];
#pragma unroll
            for (int j = 0; j < 2; j++) {
                uint32_t b0 = b_lane + buf * BBUFB + (ks * 16) * BROWB + (wn * 32 + j * 16) * 2;
                ldm_x4_t(bh[j], b0);
                ldm_x4_t(bl[j], b0 + BCHUNKB);
            }
#pragma unroll
            for (int mt = 0; mt < 2; mt++)
#pragma unroll
                for (int nt = 0; nt < 4; nt++) {
                    const uint32_t* bhp = &bh[nt >> 1][(nt & 1) * 2];
                    const uint32_t* blp = &bl[nt >> 1][(nt & 1) * 2];
                    mma_bf16(acc[mt][nt], ah[mt], bhp);
                    mma_bf16(acc[mt][nt], al[mt], bhp);
                    mma_bf16(acc[mt][nt], ah[mt], blp);
                }
        }
    }

#pragma unroll
    for (int mt = 0; mt < 2; mt++) {
        int r0 = m0g + wm * 32 + mt * 16 + g;
        int r1 = r0 + 8;
        float bv0 = bias[r0], bv1 = bias[r1];
        float* d0 = g_qkv + (size_t)b * (QKVC * HW) + (size_t)r0 * HW + nb;
        float* d1 = g_qkv + (size_t)b * (QKVC * HW) + (size_t)r1 * HW + nb;
#pragma unroll
        for (int nt = 0; nt < 4; nt++) {
            int c = wn * 32 + nt * 8 + tg * 2;
            *(float2*)(d0 + c) = make_float2(acc[mt][nt][0] + bv0, acc[mt][nt][1] + bv0);
            *(float2*)(d1 + c) = make_float2(acc[mt][nt][2] + bv1, acc[mt][nt][3] + bv1);
        }
    }
}

// ---------------------------------------------------------------------------
// Kernel 2: fused unfold-conv + slide attention (unchanged; bf16 hi/lo out)
// ---------------------------------------------------------------------------
#define TS 32
#define HAL (TS + 2)
#define HALN (HAL * HAL)

__global__ __launch_bounds__(256) void attn_kernel(
    const float* __restrict__ w1g, const float* __restrict__ b0g,
    const float* __restrict__ b1g, const float* __restrict__ rpbg)
{
    __shared__ float hs[CPHn][HAL][HAL];
    __shared__ float w1p[72 * 12];
    __shared__ float rpb[9];

    const int tile = blockIdx.x;
    const int n    = blockIdx.y;
    const int b    = blockIdx.z;
    const int ty0  = (tile >> 1) * TS;
    const int tx0  = (tile & 1) * TS;
    const int tid  = threadIdx.x;
    const int tx   = tid & 31;
    const int tr   = tid >> 5;

    for (int i = tid; i < 648; i += 256) {
        int e = i / 9, t = i - e * 9;
        w1p[e * 12 + t] = w1g[i];
    }
    if (tid < 72) w1p[tid * 12 + 9] = b0g[tid] + b1g[tid];
    if (tid < 9)  rpb[tid] = rpbg[n * 9 + tid];

    const size_t hbase = (size_t)b * (QKVC * HW) + (size_t)(n * 24) * HW;
    const float* base_q = g_qkv + hbase;
    const float* base_k = g_qkv + hbase + (size_t)8  * HW;
    const float* base_v = g_qkv + hbase + (size_t)16 * HW;

    const int hw0 = (ty0 + tr * 4) * IMG + (tx0 + tx);

    float qv[CPHn][4];
    float qsum[4] = {0.f, 0.f, 0.f, 0.f};
#pragma unroll
    for (int g = 0; g < CPHn; g++) {
        const float* qp = base_q + (size_t)g * HW + hw0;
#pragma unroll
        for (int p = 0; p < 4; p++) {
            qv[g][p] = qp[p * IMG] * SCALE;
            qsum[p] += qv[g][p];
        }
    }

#pragma unroll
    for (int g = 0; g < CPHn; g++) {
        const float* src = base_k + (size_t)g * HW;
        for (int i = tid; i < HALN; i += 256) {
            int hy = i / HAL, hx = i - hy * HAL;
            int gy = ty0 - 1 + hy, gx = tx0 - 1 + hx;
            bool ok = (unsigned)gy < 64u && (unsigned)gx < 64u;
            ((float*)hs)[g * HALN + i] = ok ? src[gy * IMG + gx] : 0.f;
        }
    }
    __syncthreads();

    float lg[4][9];
#pragma unroll
    for (int p = 0; p < 4; p++)
#pragma unroll
        for (int j = 0; j < 9; j++) lg[p][j] = rpb[j] * qsum[p];

#pragma unroll
    for (int g = 0; g < CPHn; g++) {
        float t[6][3];
#pragma unroll
        for (int rr = 0; rr < 6; rr++)
#pragma unroll
            for (int cc = 0; cc < 3; cc++)
                t[rr][cc] = hs[g][tr * 4 + rr][tx + cc];
#pragma unroll
        for (int j = 0; j < 9; j++) {
            const int jh = j / 3, jw = j % 3;
            const int wb = (g * 9 + j) * 12;
            float4 wa = *(const float4*)&w1p[wb];
            float4 wc = *(const float4*)&w1p[wb + 4];
            float4 we = *(const float4*)&w1p[wb + 8];
#pragma unroll
            for (int p = 0; p < 4; p++) {
                float kj = t[p + jh][jw] + we.y;
                kj = fmaf(wa.x, t[p][0], kj);
                kj = fmaf(wa.y, t[p][1], kj);
                kj = fmaf(wa.z, t[p][2], kj);
                kj = fmaf(wa.w, t[p + 1][0], kj);
                kj = fmaf(wc.x, t[p + 1][1], kj);
                kj = fmaf(wc.y, t[p + 1][2], kj);
                kj = fmaf(wc.z, t[p + 2][0], kj);
                kj = fmaf(wc.w, t[p + 2][1], kj);
                kj = fmaf(we.x, t[p + 2][2], kj);
                lg[p][j] = fmaf(qv[g][p], kj, lg[p][j]);
            }
        }
    }

#pragma unroll
    for (int p = 0; p < 4; p++) {
        float mx = lg[p][0];
#pragma unroll
        for (int j = 1; j < 9; j++) mx = fmaxf(mx, lg[p][j]);
        float s = 0.f;
#pragma unroll
        for (int j = 0; j < 9; j++) { lg[p][j] = __expf(lg[p][j] - mx); s += lg[p][j]; }
        float inv = 1.f / s;
#pragma unroll
        for (int j = 0; j < 9; j++) lg[p][j] *= inv;
    }

    __syncthreads();
#pragma unroll
    for (int g = 0; g < CPHn; g++) {
        const float* src = base_v + (size_t)g * HW;
        for (int i = tid; i < HALN; i += 256) {
            int hy = i / HAL, hx = i - hy * HAL;
            int gy = ty0 - 1 + hy, gx = tx0 - 1 + hx;
            bool ok = (unsigned)gy < 64u && (unsigned)gx < 64u;
            ((float*)hs)[g * HALN + i] = ok ? src[gy * IMG + gx] : 0.f;
        }
    }
    __syncthreads();

    const size_t obase = (size_t)b * (CRn * HW) + (size_t)(n * CPHn) * HW + hw0;
#pragma unroll
    for (int g = 0; g < CPHn; g++) {
        float t[6][3];
#pragma unroll
        for (int rr = 0; rr < 6; rr++)
#pragma unroll
            for (int cc = 0; cc < 3; cc++)
                t[rr][cc] = hs[g][tr * 4 + rr][tx + cc];
        float og[4] = {0.f, 0.f, 0.f, 0.f};
#pragma unroll
        for (int j = 0; j < 9; j++) {
            const int jh = j / 3, jw = j % 3;
            const int wb = (g * 9 + j) * 12;
            float4 wa = *(const float4*)&w1p[wb];
            float4 wc = *(const float4*)&w1p[wb + 4];
            float4 we = *(const float4*)&w1p[wb + 8];
#pragma unroll
            for (int p = 0; p < 4; p++) {
                float vj = t[p + jh][jw] + we.y;
                vj = fmaf(wa.x, t[p][0], vj);
                vj = fmaf(wa.y, t[p][1], vj);
                vj = fmaf(wa.z, t[p][2], vj);
                vj = fmaf(wa.w, t[p + 1][0], vj);
                vj = fmaf(wc.x, t[p + 1][1], vj);
                vj = fmaf(wc.y, t[p + 1][2], vj);
                vj = fmaf(wc.z, t[p + 2][0], vj);
                vj = fmaf(wc.w, t[p + 2][1], vj);
                vj = fmaf(we.x, t[p + 2][2], vj);
                og[p] = fmaf(lg[p][j], vj, og[p]);
            }
        }
        __nv_bfloat16* oph = g_ohi + obase + (size_t)g * HW;
        __nv_bfloat16* opl = g_olo + obase + (size_t)g * HW;
#pragma unroll
        for (int p = 0; p < 4; p++) {
            __nv_bfloat16 h = __float2bfloat16(og[p]);
            __nv_bfloat16 l = __float2bfloat16(og[p] - __bfloat162float(h));
            oph[p * IMG] = h;
            opl[p * IMG] = l;
        }
    }
}

// ---------------------------------------------------------------------------
// Kernel 3: projection GEMM (mma.sync bf16-split, ldmatrix + single-shot B)
// M=256 (4 tiles of 64), K=64 (all resident in smem).
// ---------------------------------------------------------------------------
#define AST2  72
#define AROW2B (AST2 * 2)           // 144 bytes
#define A2_ELE (2 * 64 * AST2)      // elements
#define BFULLB (64 * BROWB)         // 17408 bytes per s
#define PROJ_SMEM (A2_ELE * 2 + 2 * BFULLB)   // 18432 + 34816 = 53248

__global__ __launch_bounds__(256) void proj_mma_kernel(
    const float* __restrict__ W, const float* __restrict__ bias,
    float* __restrict__ OUT)
{
    extern __shared__ __nv_bfloat16 sm2[];
    __nv_bfloat16* As = sm2;
    __nv_bfloat16* Bs = sm2 + A2_ELE;

    const int tid  = threadIdx.x;
    const int wid  = tid >> 5;
    const int lane = tid & 31;
    const int wm   = wid & 1;
    const int wn   = wid >> 1;
    const int g    = lane >> 2;
    const int tg   = lane & 3;

    const int m0g  = blockIdx.y * 64;
    const int col0 = blockIdx.x * 128;
    const int b    = col0 >> 12;
    const int nb   = col0 & 4095;

    const __nv_bfloat16* xh = g_ohi + ((size_t)b * CRn) * HW + nb;
    const __nv_bfloat16* xl = g_olo + ((size_t)b * CRn) * HW + nb;
    const uint32_t bs_b = (uint32_t)__cvta_generic_to_shared(Bs);

    // ---- load full B (64 k rows x 128 n, hi+lo) via cp.async ----
#pragma unroll
    for (int it = 0; it < 8; it++) {
        int idx = tid + it * 256;           // 2048 16B ops
        int ss = idx >> 10, r = (idx >> 4) & 63, q = idx & 15;
        const __nv_bfloat16* src = (ss ? xl : xh) + (size_t)r * HW + q * 8;
        cp16(bs_b + ss * BFULLB + r * BROWB + q * 16, src);
    }
    CP_COMMIT();

    // ---- load W block (64 x 64), split hi/lo ----
#pragma unroll
    for (int i = 0; i < 8; i++) {
        int idx = tid + i * 256;
        int m  = idx >> 5;
        int kp = idx & 31;
        float2 w = *(const float2*)(W + (size_t)(m0g + m) * CRn + kp * 2);
        __nv_bfloat16 h0 = __float2bfloat16(w.x);
        __nv_bfloat16 h1 = __float2bfloat16(w.y);
        __nv_bfloat16 l0 = __float2bfloat16(w.x - __bfloat162float(h0));
        __nv_bfloat16 l1 = __float2bfloat16(w.y - __bfloat162float(h1));
        __nv_bfloat162 hh(h0, h1), ll(l0, l1);
        *(uint32_t*)&As[(size_t)m * AST2 + kp * 2]        = *(uint32_t*)&hh;
        *(uint32_t*)&As[(size_t)(64 + m) * AST2 + kp * 2] = *(uint32_t*)&ll;
    }

    const uint32_t a_lane = (uint32_t)__cvta_generic_to_shared(As)
                          + (lane & 15) * AROW2B + (lane >> 4) * 16;
    const uint32_t b_lane = bs_b + (lane & 15) * BROWB + (lane >> 4) * 16;

    float acc[2][4][4];
#pragma unroll
    for (int mt = 0; mt < 2; mt++)
#pragma unroll
        for (int nt = 0; nt < 4; nt++)
#pragma unroll
            for (int r = 0; r < 4; r++) acc[mt][nt][r] = 0.f;

    CP_WAIT0();
    __syncthreads();

#pragma unroll
    for (int ks = 0; ks < 4; ks++) {
        const int k0 = ks * 16;
        uint32_t ah[2][4], al[2][4];
#pragma unroll
        for (int mt = 0; mt < 2; mt++) {
            uint32_t a0 = a_lane + (wm * 32 + mt * 16) * AROW2B + k0 * 2;
            ldm_x4(ah[mt], a0);
            ldm_x4(al[mt], a0 + 64 * AROW2B);
        }
        uint32_t bh[2][4], bl[2][4];
#pragma unroll
        for (int j = 0; j < 2; j++) {
            uint32_t b0 = b_lane + k0 * BROWB + (wn * 32 + j * 16) * 2;
            ldm_x4_t(bh[j], b0);
            ldm_x4_t(bl[j], b0 + BFULLB);
        }
#pragma unroll
        for (int mt = 0; mt < 2; mt++)
#pragma unroll
            for (int nt = 0; nt < 4; nt++) {
                const uint32_t* bhp = &bh[nt >> 1][(nt & 1) * 2];
                const uint32_t* blp = &bl[nt >> 1][(nt & 1) * 2];
                mma_bf16(acc[mt][nt], ah[mt], bhp);
                mma_bf16(acc[mt][nt], al[mt], bhp);
                mma_bf16(acc[mt][nt], ah[mt], blp);
            }
    }

#pragma unroll
    for (int mt = 0; mt < 2; mt++) {
        int r0 = m0g + wm * 32 + mt * 16 + g;
        int r1 = r0 + 8;
        float bv0 = bias[r0], bv1 = bias[r1];
        float* d0 = OUT + (size_t)b * (DIMC * HW) + (size_t)r0 * HW + nb;
        float* d1 = OUT + (size_t)b * (DIMC * HW) + (size_t)r1 * HW + nb;
#pragma unroll
        for (int nt = 0; nt < 4; nt++) {
            int c = wn * 32 + nt * 8 + tg * 2;
            *(float2*)(d0 + c) = make_float2(acc[mt][nt][0] + bv0, acc[mt][nt][1] + bv0);
            *(float2*)(d1 + c) = make_float2(acc[mt][nt][2] + bv1, acc[mt][nt][3] + bv1);
        }
    }
}

// ---------------------------------------------------------------------------
// Launch. Inputs: 0:x 1:H22 2:W22 3:rpi 4:rct 5:qkv_w 6:qkv_b 7:dep_conv_b
// 8:dep_conv1_w 9:dep_conv1_b 10:rpb_table 11:proj_w 12:proj_b
// ---------------------------------------------------------------------------
extern "C" void kernel_launch(void* const* d_in, const int* in_sizes, int n_in,
                              void* d_out, int out_size)
{
    const float* x      = (const float*)d_in[0];
    const float* qkv_w  = (const float*)d_in[5];
    const float* qkv_b  = (const float*)d_in[6];
    const float* dcb    = (const float*)d_in[7];
    const float* dc1w   = (const float*)d_in[8];
    const float* dc1b   = (const float*)d_in[9];
    const float* rpb    = (const float*)d_in[10];
    const float* proj_w = (const float*)d_in[11];
    const float* proj_b = (const float*)d_in[12];
    float* out = (float*)d_out;

    static int smem_set = 0;
    if (!smem_set) {
        cudaFuncSetAttribute(qkv_mma_kernel, cudaFuncAttributeMaxDynamicSharedMemorySize, QKV_SMEM);
        cudaFuncSetAttribute(proj_mma_kernel, cudaFuncAttributeMaxDynamicSharedMemorySize, PROJ_SMEM);
        smem_set = 1;
    }

    split_x_kernel<<<16384, 256>>>(x);
    qkv_mma_kernel<<<dim3(512, 3), 256, QKV_SMEM>>>(qkv_w, qkv_b);
    attn_kernel<<<dim3(4, NHn, Bn), 256>>>(dc1w, dcb, dc1b, rpb);
    proj_mma_kernel<<<dim3(512, 4), 256, PROJ_SMEM>>>(proj_w, proj_b, out);
}